// round 14
// baseline (speedup 1.0000x reference)
#include <cuda_runtime.h>
#include <cuda_bf16.h>
#include <math.h>
#include <stdint.h>

#define Ss 1024
#define Hh 16
#define BH 32
#define LD 40
typedef __nv_bfloat16 bf;
typedef unsigned int u32;

#define OFF_PRED (2048*1024)
#define OFF_TRUE (OFF_PRED + 32*1024*1024)
#define TS (128*LD)
#define HT (64*LD)

// ---------------- scratch ----------------
__device__ bf g_qhi[BH*Ss*64], g_qlo[BH*Ss*64];     // prescaled by 1/8
__device__ bf g_khi[BH*Ss*64], g_klo[BH*Ss*64];
__device__ bf g_vhi[BH*Ss*64], g_vlo[BH*Ss*64];     // [bh][s][d]
__device__ bf g_vthi[BH*64*Ss], g_vtlo[BH*64*Ss];   // [bh][d][s]
__device__ bf g_Xhi[2048*1024], g_Xlo[2048*1024];
__device__ bf g_Whi[4][1024*1024], g_Wlo[4][1024*1024];
__device__ bf g_fqhi[BH*Ss*128];                    // bf16 features (hi only)
__device__ bf g_fkhi[BH*Ss*128];
__device__ bf g_chi[BH*Ss*64], g_clo[BH*Ss*64];
__device__ float g_fks[BH*128];

// ---------------- helpers ----------------
__device__ __forceinline__ u32 s2u(const void* p) {
    u32 r; asm("{ .reg .u64 t; cvta.to.shared.u64 t, %1; cvt.u32.u64 %0, t; }" : "=r"(r) : "l"(p)); return r;
}
__device__ __forceinline__ void cpa16(u32 dst, const void* src) {
    asm volatile("cp.async.cg.shared.global [%0], [%1], 16;" :: "r"(dst), "l"(src));
}
__device__ __forceinline__ void cpcommit() { asm volatile("cp.async.commit_group;" ::: "memory"); }
__device__ __forceinline__ void cpwait0() { asm volatile("cp.async.wait_group 0;" ::: "memory"); }
__device__ __forceinline__ void cpwait1() { asm volatile("cp.async.wait_group 1;" ::: "memory"); }
__device__ __forceinline__ void cpwait2() { asm volatile("cp.async.wait_group 2;" ::: "memory"); }
__device__ __forceinline__ void ldsm4(u32 a, u32& r0, u32& r1, u32& r2, u32& r3) {
    asm volatile("ldmatrix.sync.aligned.m8n8.x4.shared.b16 {%0,%1,%2,%3}, [%4];"
        : "=r"(r0), "=r"(r1), "=r"(r2), "=r"(r3) : "r"(a));
}
__device__ __forceinline__ void mmabf(float* d, const u32* a, const u32* b) {
    asm volatile("mma.sync.aligned.m16n8k16.row.col.f32.bf16.bf16.f32 "
        "{%0,%1,%2,%3}, {%4,%5,%6,%7}, {%8,%9}, {%0,%1,%2,%3};"
        : "+f"(d[0]), "+f"(d[1]), "+f"(d[2]), "+f"(d[3])
        : "r"(a[0]), "r"(a[1]), "r"(a[2]), "r"(a[3]), "r"(b[0]), "r"(b[1]));
}
__device__ __forceinline__ void split2(float x, float y, u32& hi, u32& lo) {
    bf hx = __float2bfloat16(x), hy = __float2bfloat16(y);
    bf lx = __float2bfloat16(x - __bfloat162float(hx));
    bf ly = __float2bfloat16(y - __bfloat162float(hy));
    hi = (u32)__bfloat16_as_ushort(hx) | ((u32)__bfloat16_as_ushort(hy) << 16);
    lo = (u32)__bfloat16_as_ushort(lx) | ((u32)__bfloat16_as_ushort(ly) << 16);
}
// fast exp on FMA pipe (rel err ~2e-6)
__device__ __forceinline__ float fexp(float x) {
    float t = x * 1.4426950408889634f;
    float f = t + 12582912.0f;
    int ib = __float_as_int(f);
    float n = f - 12582912.0f;
    float r = t - n;
    float p = 1.3333558e-3f;
    p = fmaf(p, r, 9.6181291e-3f);
    p = fmaf(p, r, 5.5504109e-2f);
    p = fmaf(p, r, 2.4022651e-1f);
    p = fmaf(p, r, 6.9314718e-1f);
    p = fmaf(p, r, 1.0f);
    return p * __int_as_float((ib << 23) + 0x3F800000);
}

__device__ __forceinline__ void ldtile32a(const bf* __restrict__ g, int ldg, u32 s, int rows) {
    for (int i = threadIdx.x; i < rows * 4; i += 256) {
        int r = i >> 2, c = (i & 3) << 3;
        cpa16(s + (u32)((r * LD + c) << 1), g + (size_t)r * ldg + c);
    }
}

// 3-product hi/lo emulation chunk
template<int NF>
__device__ __forceinline__ void mma_chunk(
    float (&acc)[2][NF][4],
    const bf* Ah, const bf* Al, const bf* Bh, const bf* Bl,
    int wm, int wn, int lane)
{
    const u32 ahb = s2u(Ah) + (u32)(wm * 32 * LD * 2);
    const u32 alb = s2u(Al) + (u32)(wm * 32 * LD * 2);
    const u32 bhb = s2u(Bh) + (u32)(wn * NF * 8 * LD * 2);
    const u32 blb = s2u(Bl) + (u32)(wn * NF * 8 * LD * 2);
    const u32 aoff = (u32)(((lane & 15) * LD + ((lane >> 4) << 3)) * 2);
    const u32 boff = (u32)((((lane & 7) + ((lane >> 4) << 3)) * LD + (((lane >> 3) & 1) << 3)) * 2);
    #pragma unroll
    for (int kk = 0; kk < 32; kk += 16) {
        u32 ah[2][4], al[2][4], bhf[NF][2], blf[NF][2];
        #pragma unroll
        for (int i = 0; i < 2; i++) {
            ldsm4(ahb + aoff + kk * 2 + i * 16 * LD * 2, ah[i][0], ah[i][1], ah[i][2], ah[i][3]);
            ldsm4(alb + aoff + kk * 2 + i * 16 * LD * 2, al[i][0], al[i][1], al[i][2], al[i][3]);
        }
        #pragma unroll
        for (int j = 0; j < NF; j += 2) {
            ldsm4(bhb + boff + kk * 2 + j * 8 * LD * 2, bhf[j][0], bhf[j][1], bhf[j+1][0], bhf[j+1][1]);
            ldsm4(blb + boff + kk * 2 + j * 8 * LD * 2, blf[j][0], blf[j][1], blf[j+1][0], blf[j+1][1]);
        }
        #pragma unroll
        for (int i = 0; i < 2; i++)
            #pragma unroll
            for (int j = 0; j < NF; j++) {
                mmabf(acc[i][j], ah[i], bhf[j]);
                mmabf(acc[i][j], ah[i], blf[j]);
                mmabf(acc[i][j], al[i], bhf[j]);
            }
    }
}

// 1-product plain bf16 chunk (pred path)
template<int NF>
__device__ __forceinline__ void mma_chunk1(
    float (&acc)[2][NF][4],
    const bf* A, const bf* B,
    int wm, int wn, int lane)
{
    const u32 ab = s2u(A) + (u32)(wm * 32 * LD * 2);
    const u32 bb = s2u(B) + (u32)(wn * NF * 8 * LD * 2);
    const u32 aoff = (u32)(((lane & 15) * LD + ((lane >> 4) << 3)) * 2);
    const u32 boff = (u32)((((lane & 7) + ((lane >> 4) << 3)) * LD + (((lane >> 3) & 1) << 3)) * 2);
    #pragma unroll
    for (int kk = 0; kk < 32; kk += 16) {
        u32 a[2][4], bfr[NF][2];
        #pragma unroll
        for (int i = 0; i < 2; i++)
            ldsm4(ab + aoff + kk * 2 + i * 16 * LD * 2, a[i][0], a[i][1], a[i][2], a[i][3]);
        #pragma unroll
        for (int j = 0; j < NF; j += 2)
            ldsm4(bb + boff + kk * 2 + j * 8 * LD * 2, bfr[j][0], bfr[j][1], bfr[j+1][0], bfr[j+1][1]);
        #pragma unroll
        for (int i = 0; i < 2; i++)
            #pragma unroll
            for (int j = 0; j < NF; j++)
                mmabf(acc[i][j], a[i], bfr[j]);
    }
}

extern __shared__ __align__(16) char dynsm[];

// ============================================================
__global__ __launch_bounds__(256) void ksplit_all(
    const float* __restrict__ hs, const float* __restrict__ Wq,
    const float* __restrict__ Wk, const float* __restrict__ Wv,
    const float* __restrict__ Wo)
{
    const int y = blockIdx.y;
    const float* src; bf* hi; bf* lo; int n4;
    if (y == 0)      { src = hs; hi = g_Xhi;    lo = g_Xlo;    n4 = 524288; }
    else if (y == 1) { src = Wq; hi = g_Whi[0]; lo = g_Wlo[0]; n4 = 262144; }
    else if (y == 2) { src = Wk; hi = g_Whi[1]; lo = g_Wlo[1]; n4 = 262144; }
    else if (y == 3) { src = Wv; hi = g_Whi[2]; lo = g_Wlo[2]; n4 = 262144; }
    else             { src = Wo; hi = g_Whi[3]; lo = g_Wlo[3]; n4 = 262144; }
    int i = blockIdx.x * 256 + threadIdx.x;
    if (i < n4) {
        float4 v = ((const float4*)src)[i];
        u32 h0, l0, h1, l1;
        split2(v.x, v.y, h0, l0);
        split2(v.z, v.w, h1, l1);
        ((uint2*)hi)[i] = make_uint2(h0, h1);
        ((uint2*)lo)[i] = make_uint2(l0, l1);
    }
}

// ============================================================
// QKV. grid(8n,16m,3z). 2-stage pipeline, 80KB smem, 2 CTAs/SM.
// ============================================================
__global__ __launch_bounds__(256, 2) void qkv_mma(
    const float* __restrict__ bq, const float* __restrict__ bk, const float* __restrict__ bv)
{
    bf* buf = (bf*)dynsm;
    const int tid = threadIdx.x, lane = tid & 31, wid = tid >> 5;
    const int wm = wid & 3, wn = wid >> 2;
    const int g = lane >> 2, ti = lane & 3;
    const int z = blockIdx.z, m0 = blockIdx.y * 128, n0 = blockIdx.x * 128;
    const bf* Whi = g_Whi[z]; const bf* Wlo = g_Wlo[z];
    const float* bias = z == 0 ? bq : (z == 1 ? bk : bv);

    float acc[2][8][4];
    #pragma unroll
    for (int i = 0; i < 2; i++)
        #pragma unroll
        for (int j = 0; j < 8; j++)
            #pragma unroll
            for (int r = 0; r < 4; r++) acc[i][j][r] = 0.f;

    auto issue = [&](int c) {
        bf* p = buf + (c & 1) * 4 * TS;
        const int k0 = c * 32;
        ldtile32a(g_Xhi + (size_t)m0 * 1024 + k0, 1024, s2u(p), 128);
        ldtile32a(g_Xlo + (size_t)m0 * 1024 + k0, 1024, s2u(p + TS), 128);
        ldtile32a(Whi + (size_t)n0 * 1024 + k0, 1024, s2u(p + 2 * TS), 128);
        ldtile32a(Wlo + (size_t)n0 * 1024 + k0, 1024, s2u(p + 3 * TS), 128);
        cpcommit();
    };
    issue(0); issue(1);

    for (int c = 0; c < 32; c++) {
        if (c == 31) cpwait0(); else cpwait1();
        __syncthreads();
        bf* p = buf + (c & 1) * 4 * TS;
        mma_chunk<8>(acc, p, p + TS, p + 2 * TS, p + 3 * TS, wm, wn, lane);
        __syncthreads();
        if (c + 2 < 32) issue(c + 2);
    }

    #pragma unroll
    for (int i = 0; i < 2; i++)
        #pragma unroll
        for (int j = 0; j < 8; j++) {
            const int col = n0 + wn * 64 + j * 8 + ti * 2;
            const int h = col >> 6, d = col & 63;
            const float b0v = bias[col], b1v = bias[col + 1];
            #pragma unroll
            for (int hr = 0; hr < 2; hr++) {
                const int row = m0 + wm * 32 + i * 16 + g + hr * 8;
                const int b_ = row >> 10, s = row & 1023;
                const size_t ob = ((size_t)(b_ * Hh + h) * Ss + s) * 64 + d;
                const float v0 = acc[i][j][hr * 2] + b0v, v1 = acc[i][j][hr * 2 + 1] + b1v;
                u32 h2, l2;
                if (z == 0) {
                    split2(v0 * 0.125f, v1 * 0.125f, h2, l2);
                    *(u32*)&g_qhi[ob] = h2; *(u32*)&g_qlo[ob] = l2;
                } else if (z == 1) {
                    split2(v0, v1, h2, l2);
                    *(u32*)&g_khi[ob] = h2; *(u32*)&g_klo[ob] = l2;
                } else {
                    split2(v0, v1, h2, l2);
                    *(u32*)&g_vhi[ob] = h2; *(u32*)&g_vlo[ob] = l2;
                }
            }
        }
}

// ============================================================
// feature map from split q/k -> bf16 features (hi only), all-fexp
// ============================================================
__global__ __launch_bounds__(256) void feat_kernel(
    const float* __restrict__ Wfq, const float* __restrict__ bfq,
    const float* __restrict__ Wfk, const float* __restrict__ bfk)
{
    const float* Wf; const float* bfp; const bf *sh, *sl; float scale; bf* dh;
    if (blockIdx.y == 0) { Wf = Wfq; bfp = bfq; sh = g_qhi; sl = g_qlo; scale = 8.f; dh = g_fqhi; }
    else                 { Wf = Wfk; bfp = bfk; sh = g_khi; sl = g_klo; scale = 1.f; dh = g_fkhi; }

    __shared__ float Wt[64][65];
    __shared__ float bsm[64];
    __shared__ float qs[4][64];

    const int tid = threadIdx.x;
    #pragma unroll
    for (int p = 0; p < 16; p++) {
        int idx = p * 256 + tid;
        Wt[idx & 63][idx >> 6] = Wf[idx];
    }
    if (tid < 64) bsm[tid] = bfp[tid];

    const int rowbase = blockIdx.x * 128;
    const int e = tid & 63, rr = tid >> 6;

    for (int r0 = 0; r0 < 128; r0 += 4) {
        __syncthreads();
        int row = rowbase + r0 + rr;
        size_t so = (size_t)row * 64 + e;
        qs[rr][e] = (__bfloat162float(sh[so]) + __bfloat162float(sl[so])) * scale;
        __syncthreads();
        float y = bsm[e];
        #pragma unroll
        for (int d = 0; d < 64; d++) y += Wt[d][e] * qs[rr][d];
        float e0 = fexp(y), e1 = fexp(-y);
        size_t o = (size_t)row * 128 + e;
        dh[o]      = __float2bfloat16(e0);
        dh[o + 64] = __float2bfloat16(e1);
    }
}

// ============================================================
// V transpose (plane-wise, bf16): [bh][s][64] -> [bh][64][s]
// ============================================================
__global__ __launch_bounds__(256) void vtrans()
{
    __shared__ bf t[128][72];
    const int bh = blockIdx.x, s0 = blockIdx.y * 128, tid = threadIdx.x;
    #pragma unroll
    for (int a = 0; a < 2; a++) {
        const bf* src = a ? g_vlo : g_vhi;
        bf* dst = a ? g_vtlo : g_vthi;
        __syncthreads();
        for (int i = tid; i < 1024; i += 256) {
            int r = i >> 3, d8 = (i & 7) * 8;
            *(uint4*)&t[r][d8] = *(const uint4*)(src + ((size_t)bh * Ss + s0 + r) * 64 + d8);
        }
        __syncthreads();
        {
            const int d = tid & 63, sg = tid >> 6;
            __align__(16) bf tmp[32];
            #pragma unroll
            for (int s = 0; s < 32; s++) tmp[s] = t[sg * 32 + s][d];
            uint4* dp = (uint4*)(dst + ((size_t)bh * 64 + d) * Ss + s0 + sg * 32);
            #pragma unroll
            for (int q = 0; q < 4; q++) dp[q] = ((uint4*)tmp)[q];
        }
    }
}

// ============================================================
__global__ __launch_bounds__(256) void fksum_kernel()
{
    const int bh = blockIdx.x, tid = threadIdx.x;
    const int e = tid & 127, part = tid >> 7;
    const bf* fh = g_fkhi + (size_t)bh * Ss * 128;
    float s = 0.f;
    for (int r = part; r < 1024; r += 2)
        s += __bfloat162float(fh[(size_t)r * 128 + e]);
    __shared__ float sm[256];
    sm[tid] = s;
    __syncthreads();
    if (tid < 128) g_fks[bh * 128 + tid] = sm[tid] + sm[tid + 128];
}

// ============================================================
// FUSED true attention + ctx, recompute-S two-pass.
// Pass A: S MMA + fexp + rowsum (no stores).
// Pass B: S MMA again, fexp*inv, write normalized trow ONCE,
//         FA2-repack P, accumulate ctx with co-streamed V.
// Q resident 40KB + 3 stages x (K 20KB + V 20KB) = 160KB, 1 CTA/SM.
// ============================================================
__global__ __launch_bounds__(256) void true_fused(float* __restrict__ outT)
{
    bf* qb = (bf*)dynsm;                 // 4*TS
    bf* kb = (bf*)dynsm + 4 * TS;        // 3 stages x 8*HT (K:4HT then V:4HT)
    __shared__ float rs[128];
    __shared__ float invs[128];
    const int tid = threadIdx.x, lane = tid & 31, wid = tid >> 5;
    const int wm = wid & 3, wn = wid >> 2;
    const int g = lane >> 2, ti = lane & 3;
    const int bh = blockIdx.y, m0 = blockIdx.x * 128;
    float* trow = outT + (size_t)bh * Ss * Ss;
    const bf* qh = g_qhi + ((size_t)bh * Ss + m0) * 64;
    const bf* ql = g_qlo + ((size_t)bh * Ss + m0) * 64;

    if (tid < 128) rs[tid] = 0.f;

    ldtile32a(qh,      64, s2u(qb),          128);
    ldtile32a(ql,      64, s2u(qb + TS),     128);
    ldtile32a(qh + 32, 64, s2u(qb + 2 * TS), 128);
    ldtile32a(ql + 32, 64, s2u(qb + 3 * TS), 128);
    cpcommit();

    auto issueKA = [&](int nt) {   // K only
        bf* p = kb + (nt % 3) * 8 * HT;
        const bf* kh = g_khi + ((size_t)bh * Ss + nt * 64) * 64;
        const bf* kl = g_klo + ((size_t)bh * Ss + nt * 64) * 64;
        ldtile32a(kh,      64, s2u(p),          64);
        ldtile32a(kl,      64, s2u(p + HT),     64);
        ldtile32a(kh + 32, 64, s2u(p + 2 * HT), 64);
        ldtile32a(kl + 32, 64, s2u(p + 3 * HT), 64);
        cpcommit();
    };
    auto issueKV = [&](int nt) {   // K + V
        bf* p = kb + (nt % 3) * 8 * HT;
        const bf* kh = g_khi + ((size_t)bh * Ss + nt * 64) * 64;
        const bf* kl = g_klo + ((size_t)bh * Ss + nt * 64) * 64;
        ldtile32a(kh,      64, s2u(p),          64);
        ldtile32a(kl,      64, s2u(p + HT),     64);
        ldtile32a(kh + 32, 64, s2u(p + 2 * HT), 64);
        ldtile32a(kl + 32, 64, s2u(p + 3 * HT), 64);
        bf* vp = p + 4 * HT;
        const bf* vh = g_vthi + (size_t)bh * 64 * Ss + nt * 64;
        const bf* vl = g_vtlo + (size_t)bh * 64 * Ss + nt * 64;
        ldtile32a(vh,      Ss, s2u(vp),          64);   // s chunk 0 (hi)
        ldtile32a(vh + 32, Ss, s2u(vp + HT),     64);   // s chunk 1 (hi)
        ldtile32a(vl,      Ss, s2u(vp + 2 * HT), 64);   // s chunk 0 (lo)
        ldtile32a(vl + 32, Ss, s2u(vp + 3 * HT), 64);   // s chunk 1 (lo)
        cpcommit();
    };

    // ---------------- pass A: rowsums only ----------------
    issueKA(0); issueKA(1); issueKA(2);
    float rsum[4] = {0.f, 0.f, 0.f, 0.f};
    for (int nt = 0; nt < 16; nt++) {
        if (nt <= 13) cpwait2(); else if (nt == 14) cpwait1(); else cpwait0();
        __syncthreads();
        float acc[2][4][4];
        #pragma unroll
        for (int i = 0; i < 2; i++)
            #pragma unroll
            for (int j = 0; j < 4; j++)
                #pragma unroll
                for (int r = 0; r < 4; r++) acc[i][j][r] = 0.f;

        bf* p = kb + (nt % 3) * 8 * HT;
        mma_chunk<4>(acc, qb,          qb + TS,     p,          p + HT,     wm, wn, lane);
        mma_chunk<4>(acc, qb + 2 * TS, qb + 3 * TS, p + 2 * HT, p + 3 * HT, wm, wn, lane);
        __syncthreads();
        if (nt + 3 < 16) issueKA(nt + 3);

        #pragma unroll
        for (int i = 0; i < 2; i++)
            #pragma unroll
            for (int j = 0; j < 4; j++) {
                rsum[i * 2]     += fexp(acc[i][j][0]) + fexp(acc[i][j][1]);
                rsum[i * 2 + 1] += fexp(acc[i][j][2]) + fexp(acc[i][j][3]);
            }
    }
    #pragma unroll
    for (int r = 0; r < 4; r++) {
        float v = rsum[r];
        v += __shfl_xor_sync(0xffffffffu, v, 1);
        v += __shfl_xor_sync(0xffffffffu, v, 2);
        if (ti == 0) atomicAdd(&rs[wm * 32 + (r >> 1) * 16 + (r & 1) * 8 + g], v);
    }
    __syncthreads();
    if (tid < 128) invs[tid] = 1.f / rs[tid];
    __syncthreads();
    float invr[4];
    #pragma unroll
    for (int r = 0; r < 4; r++)
        invr[r] = invs[wm * 32 + (r >> 1) * 16 + (r & 1) * 8 + g];

    // ---------------- pass B: normalized store + ctx ----------------
    float accD[2][8][4];
    #pragma unroll
    for (int i = 0; i < 2; i++)
        #pragma unroll
        for (int j = 0; j < 8; j++)
            #pragma unroll
            for (int r = 0; r < 4; r++) accD[i][j][r] = 0.f;

    const u32 boff = (u32)((((lane & 7) + ((lane >> 4) << 3)) * LD + (((lane >> 3) & 1) << 3)) * 2);

    issueKV(0); issueKV(1); issueKV(2);
    for (int nt = 0; nt < 16; nt++) {
        if (nt <= 13) cpwait2(); else if (nt == 14) cpwait1(); else cpwait0();
        __syncthreads();
        float acc[2][4][4];
        #pragma unroll
        for (int i = 0; i < 2; i++)
            #pragma unroll
            for (int j = 0; j < 4; j++)
                #pragma unroll
                for (int r = 0; r < 4; r++) acc[i][j][r] = 0.f;

        bf* p = kb + (nt % 3) * 8 * HT;
        mma_chunk<4>(acc, qb,          qb + TS,     p,          p + HT,     wm, wn, lane);
        mma_chunk<4>(acc, qb + 2 * TS, qb + 3 * TS, p + 2 * HT, p + 3 * HT, wm, wn, lane);

        // exp * inv, store normalized P once
        const int n0 = nt * 64;
        #pragma unroll
        for (int i = 0; i < 2; i++)
            #pragma unroll
            for (int j = 0; j < 4; j++) {
                float e0 = fexp(acc[i][j][0]) * invr[i * 2];
                float e1 = fexp(acc[i][j][1]) * invr[i * 2];
                float e2 = fexp(acc[i][j][2]) * invr[i * 2 + 1];
                float e3 = fexp(acc[i][j][3]) * invr[i * 2 + 1];
                acc[i][j][0] = e0; acc[i][j][1] = e1; acc[i][j][2] = e2; acc[i][j][3] = e3;
                const int col = n0 + wn * 32 + j * 8 + ti * 2;
                const int row = m0 + wm * 32 + i * 16 + g;
                *(float2*)&trow[(size_t)row * 1024 + col]       = make_float2(e0, e1);
                *(float2*)&trow[(size_t)(row + 8) * 1024 + col] = make_float2(e2, e3);
            }

        // P @ V: P from registers (FA2 repack), V from this stage's smem
        bf* vp = p + 4 * HT;
        const u32 hib = s2u(vp + wn * HT);
        const u32 lob = s2u(vp + (2 + wn) * HT);
        #pragma unroll
        for (int t4 = 0; t4 < 2; t4++) {
            const u32 cb = (u32)(t4 * 16 * 2);
            u32 bhf[8][2], blf[8][2];
            #pragma unroll
            for (int j = 0; j < 8; j += 2) {
                ldsm4(hib + cb + (u32)(j * 8 * LD * 2) + boff, bhf[j][0], bhf[j][1], bhf[j+1][0], bhf[j+1][1]);
                ldsm4(lob + cb + (u32)(j * 8 * LD * 2) + boff, blf[j][0], blf[j][1], blf[j+1][0], blf[j+1][1]);
            }
            #pragma unroll
            for (int i = 0; i < 2; i++) {
                u32 ah[4], al[4];
                split2(acc[i][2*t4][0],   acc[i][2*t4][1],   ah[0], al[0]);
                split2(acc[i][2*t4][2],   acc[i][2*t4][3],   ah[1], al[1]);
                split2(acc[i][2*t4+1][0], acc[i][2*t4+1][1], ah[2], al[2]);
                split2(acc[i][2*t4+1][2], acc[i][2*t4+1][3], ah[3], al[3]);
                #pragma unroll
                for (int j = 0; j < 8; j++) {
                    mmabf(accD[i][j], ah, bhf[j]);
                    mmabf(accD[i][j], ah, blf[j]);
                    mmabf(accD[i][j], al, bhf[j]);
                }
            }
        }
        __syncthreads();                 // all stage reads done before refill
        if (nt + 3 < 16) issueKV(nt + 3);
    }

    // ---------------- epilogue: cross-warp ctx reduction ----------------
    __syncthreads();
    float* red = (float*)dynsm;          // reuse Q area (32KB needed)
    if (wn == 1) {
        #pragma unroll
        for (int i = 0; i < 2; i++)
            #pragma unroll
            for (int j = 0; j < 8; j++) {
                const int col = j * 8 + ti * 2;
                const int r0 = wm * 32 + i * 16 + g;
                red[r0 * 64 + col]           = accD[i][j][0];
                red[r0 * 64 + col + 1]       = accD[i][j][1];
                red[(r0 + 8) * 64 + col]     = accD[i][j][2];
                red[(r0 + 8) * 64 + col + 1] = accD[i][j][3];
            }
    }
    __syncthreads();
    if (wn == 0) {
        #pragma unroll
        for (int i = 0; i < 2; i++)
            #pragma unroll
            for (int j = 0; j < 8; j++) {
                const int col = j * 8 + ti * 2;
                const int r0 = wm * 32 + i * 16 + g, r1 = r0 + 8;
                float v0 = accD[i][j][0] + red[r0 * 64 + col];
                float v1 = accD[i][j][1] + red[r0 * 64 + col + 1];
                float v2 = accD[i][j][2] + red[r1 * 64 + col];
                float v3 = accD[i][j][3] + red[r1 * 64 + col + 1];
                u32 h2, l2;
                split2(v0, v1, h2, l2);
                *(u32*)&g_chi[((size_t)bh * Ss + m0 + r0) * 64 + col] = h2;
                *(u32*)&g_clo[((size_t)bh * Ss + m0 + r0) * 64 + col] = l2;
                split2(v2, v3, h2, l2);
                *(u32*)&g_chi[((size_t)bh * Ss + m0 + r1) * 64 + col] = h2;
                *(u32*)&g_clo[((size_t)bh * Ss + m0 + r1) * 64 + col] = l2;
            }
    }
}

// ============================================================
// pred: hi-only bf16 features, denom computed in-kernel from smem fq.
// fq resident 40KB, fk 3-stage half-tiles. 100KB smem -> 2 CTAs/SM.
// ============================================================
__global__ __launch_bounds__(256, 2) void pred_mma(float* __restrict__ outP)
{
    bf* fq = (bf*)dynsm;
    bf* kb = (bf*)dynsm + 4 * TS;
    __shared__ float fks_sm[128];
    __shared__ float pinv_sm[128];
    const int tid = threadIdx.x, lane = tid & 31, wid = tid >> 5;
    const int wm = wid & 3, wn = wid >> 2;
    const int g = lane >> 2, ti = lane & 3;
    const int bh = blockIdx.y, m0 = blockIdx.x * 128;
    float* prow = outP + (size_t)bh * Ss * Ss;
    const bf* fqh = g_fqhi + ((size_t)bh * Ss + m0) * 128;

    if (tid < 128) fks_sm[tid] = g_fks[bh * 128 + tid];

    #pragma unroll
    for (int kc = 0; kc < 4; kc++)
        ldtile32a(fqh + kc * 32, 128, s2u(fq + kc * TS), 128);
    cpcommit();

    auto issueFK = [&](int st) {
        bf* p = kb + (st % 3) * 2 * TS;
        const int nt = st >> 1, half = st & 1;
        const bf* kh = g_fkhi + ((size_t)bh * Ss + nt * 128) * 128 + half * 64;
        ldtile32a(kh,      128, s2u(p),      128);
        ldtile32a(kh + 32, 128, s2u(p + TS), 128);
        cpcommit();
    };
    issueFK(0); issueFK(1); issueFK(2);

    float pv[4];
    float acc[2][8][4];
    for (int st = 0; st < 16; st++) {
        const int nt = st >> 1, half = st & 1;
        if (half == 0) {
            #pragma unroll
            for (int i = 0; i < 2; i++)
                #pragma unroll
                for (int j = 0; j < 8; j++)
                    #pragma unroll
                    for (int r = 0; r < 4; r++) acc[i][j][r] = 0.f;
        }
        if (st <= 13) cpwait2(); else if (st == 14) cpwait1(); else cpwait0();
        __syncthreads();

        if (st == 0) {
            if (tid < 128) {
                float d = 0.f;
                #pragma unroll
                for (int kc = 0; kc < 4; kc++) {
                    const bf* fr = fq + kc * TS + tid * LD;
                    #pragma unroll
                    for (int kk = 0; kk < 32; kk++)
                        d += __bfloat162float(fr[kk]) * fks_sm[kc * 32 + kk];
                }
                pinv_sm[tid] = 1.f / d;
            }
            __syncthreads();
            #pragma unroll
            for (int r = 0; r < 4; r++)
                pv[r] = pinv_sm[wm * 32 + (r >> 1) * 16 + (r & 1) * 8 + g];
        }

        bf* p = kb + (st % 3) * 2 * TS;
        const int kc = half * 2;
        mma_chunk1<8>(acc, fq + kc * TS,       p,      wm, wn, lane);
        mma_chunk1<8>(acc, fq + (kc + 1) * TS, p + TS, wm, wn, lane);
        __syncthreads();
        if (st + 3 < 16) issueFK(st + 3);

        if (half == 1) {
            const int n0 = nt * 128;
            #pragma unroll
            for (int i = 0; i < 2; i++)
                #pragma unroll
                for (int j = 0; j < 8; j++) {
                    const int col = n0 + wn * 64 + j * 8 + ti * 2;
                    const int row = m0 + wm * 32 + i * 16 + g;
                    *(float2*)&prow[(size_t)row * 1024 + col] =
                        make_float2(acc[i][j][0] * pv[i * 2], acc[i][j][1] * pv[i * 2]);
                    *(float2*)&prow[(size_t)(row + 8) * 1024 + col] =
                        make_float2(acc[i][j][2] * pv[i * 2 + 1], acc[i][j][3] * pv[i * 2 + 1]);
                }
        }
    }
}

// ============================================================
// outproj. grid(8n,16m). 3-stage pipeline.
// ============================================================
__global__ __launch_bounds__(256) void outproj_mma(const float* __restrict__ bo, float* __restrict__ out)
{
    bf* buf = (bf*)dynsm;
    const int tid = threadIdx.x, lane = tid & 31, wid = tid >> 5;
    const int wm = wid & 3, wn = wid >> 2;
    const int g = lane >> 2, ti = lane & 3;
    const int m0 = blockIdx.y * 128, n0 = blockIdx.x * 128;
    const int b_ = m0 >> 10, s0 = m0 & 1023;

    float acc[2][8][4];
    #pragma unroll
    for (int i = 0; i < 2; i++)
        #pragma unroll
        for (int j = 0; j < 8; j++)
            #pragma unroll
            for (int r = 0; r < 4; r++) acc[i][j][r] = 0.f;

    auto issue = [&](int c) {
        bf* p = buf + (c % 3) * 4 * TS;
        const int k0 = c * 32;
        const int h = k0 >> 6, doff = k0 & 63;
        const size_t abase = ((size_t)(b_ * Hh + h) * Ss + s0) * 64 + doff;
        ldtile32a(g_chi + abase, 64, s2u(p), 128);
        ldtile32a(g_clo + abase, 64, s2u(p + TS), 128);
        ldtile32a(g_Whi[3] + (size_t)n0 * 1024 + k0, 1024, s2u(p + 2 * TS), 128);
        ldtile32a(g_Wlo[3] + (size_t)n0 * 1024 + k0, 1024, s2u(p + 3 * TS), 128);
        cpcommit();
    };
    issue(0); issue(1); issue(2);

    for (int c = 0; c < 32; c++) {
        if (c <= 29) cpwait2(); else if (c == 30) cpwait1(); else cpwait0();
        __syncthreads();
        bf* p = buf + (c % 3) * 4 * TS;
        mma_chunk<8>(acc, p, p + TS, p + 2 * TS, p + 3 * TS, wm, wn, lane);
        __syncthreads();
        if (c + 3 < 32) issue(c + 3);
    }

    #pragma unroll
    for (int i = 0; i < 2; i++)
        #pragma unroll
        for (int j = 0; j < 8; j++) {
            const int col = n0 + wn * 64 + j * 8 + ti * 2;
            const float b0v = bo[col], b1v = bo[col + 1];
            #pragma unroll
            for (int hr = 0; hr < 2; hr++) {
                const int row = m0 + wm * 32 + i * 16 + g + hr * 8;
                *(float2*)&out[(size_t)row * 1024 + col] =
                    make_float2(acc[i][j][hr * 2] + b0v, acc[i][j][hr * 2 + 1] + b1v);
            }
        }
}

// ============================================================
extern "C" void kernel_launch(void* const* d_in, const int* in_sizes, int n_in,
                              void* d_out, int out_size)
{
    const float* hs  = (const float*)d_in[0];
    const float* Wq  = (const float*)d_in[1];
    const float* bq  = (const float*)d_in[2];
    const float* Wk  = (const float*)d_in[3];
    const float* bk  = (const float*)d_in[4];
    const float* Wv  = (const float*)d_in[5];
    const float* bv  = (const float*)d_in[6];
    const float* Wo  = (const float*)d_in[7];
    const float* bo  = (const float*)d_in[8];
    const float* Wfq = (const float*)d_in[9];
    const float* bfq = (const float*)d_in[10];
    const float* Wfk = (const float*)d_in[11];
    const float* bfk = (const float*)d_in[12];
    float* out = (float*)d_out;

    const int SM_GEMM2 = 8 * TS * 2;                          // 81920 (2 CTA/SM)
    const int SM_GEMM3 = 12 * TS * 2;                         // 122880
    const int SM_TRUEF = 4 * TS * 2 + 24 * HT * 2;            // 163840 (1 CTA/SM)
    const int SM_PRED  = (4 + 6) * TS * 2;                    // 102400 (2 CTA/SM)
    cudaFuncSetAttribute(qkv_mma,     cudaFuncAttributeMaxDynamicSharedMemorySize, SM_GEMM2);
    cudaFuncSetAttribute(true_fused,  cudaFuncAttributeMaxDynamicSharedMemorySize, SM_TRUEF);
    cudaFuncSetAttribute(pred_mma,    cudaFuncAttributeMaxDynamicSharedMemorySize, SM_PRED);
    cudaFuncSetAttribute(outproj_mma, cudaFuncAttributeMaxDynamicSharedMemorySize, SM_GEMM3);

    cudaStream_t s2;
    cudaStreamCreateWithFlags(&s2, cudaStreamNonBlocking);
    cudaEvent_t evFork, evJoin;
    cudaEventCreateWithFlags(&evFork, cudaEventDisableTiming);
    cudaEventCreateWithFlags(&evJoin, cudaEventDisableTiming);

    ksplit_all<<<dim3(2048, 5), 256>>>(hs, Wq, Wk, Wv, Wo);
    qkv_mma<<<dim3(8, 16, 3), 256, SM_GEMM2>>>(bq, bk, bv);
    feat_kernel<<<dim3(256, 2), 256>>>(Wfq, bfq, Wfk, bfk);
    vtrans<<<dim3(32, 8), 256>>>();
    fksum_kernel<<<32, 256>>>();

    // fork: pred on side stream (independent of true path)
    cudaEventRecord(evFork, 0);
    cudaStreamWaitEvent(s2, evFork, 0);
    pred_mma<<<dim3(8, 32), 256, SM_PRED, s2>>>(out + OFF_PRED);
    cudaEventRecord(evJoin, s2);

    // main chain
    true_fused<<<dim3(8, 32), 256, SM_TRUEF>>>(out + OFF_TRUE);
    outproj_mma<<<dim3(8, 16), 256, SM_GEMM3>>>(bo, out);

    cudaStreamWaitEvent(0, evJoin, 0);
}

// round 15
// speedup vs baseline: 1.0668x; 1.0668x over previous
#include <cuda_runtime.h>
#include <cuda_bf16.h>
#include <math.h>
#include <stdint.h>

#define Ss 1024
#define Hh 16
#define BH 32
#define LD 40
typedef __nv_bfloat16 bf;
typedef unsigned int u32;

#define OFF_PRED (2048*1024)
#define OFF_TRUE (OFF_PRED + 32*1024*1024)
#define TS (128*LD)
#define HT (64*LD)

// ---------------- scratch ----------------
__device__ bf g_qhi[BH*Ss*64], g_qlo[BH*Ss*64];     // prescaled by 1/8
__device__ bf g_khi[BH*Ss*64], g_klo[BH*Ss*64];
__device__ bf g_vhi[BH*Ss*64], g_vlo[BH*Ss*64];     // [bh][s][d]
__device__ bf g_vthi[BH*64*Ss], g_vtlo[BH*64*Ss];   // [bh][d][s]
__device__ bf g_Xhi[2048*1024], g_Xlo[2048*1024];
__device__ bf g_Whi[4][1024*1024], g_Wlo[4][1024*1024];
__device__ bf g_fqhi[BH*Ss*128];                    // bf16 features (hi only)
__device__ bf g_fkhi[BH*Ss*128];
__device__ bf g_chi[BH*Ss*64], g_clo[BH*Ss*64];
__device__ float g_fks[BH*128], g_inv[BH*Ss];

// ---------------- helpers ----------------
__device__ __forceinline__ u32 s2u(const void* p) {
    u32 r; asm("{ .reg .u64 t; cvta.to.shared.u64 t, %1; cvt.u32.u64 %0, t; }" : "=r"(r) : "l"(p)); return r;
}
__device__ __forceinline__ void cpa16(u32 dst, const void* src) {
    asm volatile("cp.async.cg.shared.global [%0], [%1], 16;" :: "r"(dst), "l"(src));
}
__device__ __forceinline__ void cpcommit() { asm volatile("cp.async.commit_group;" ::: "memory"); }
__device__ __forceinline__ void cpwait0() { asm volatile("cp.async.wait_group 0;" ::: "memory"); }
__device__ __forceinline__ void cpwait1() { asm volatile("cp.async.wait_group 1;" ::: "memory"); }
__device__ __forceinline__ void cpwait2() { asm volatile("cp.async.wait_group 2;" ::: "memory"); }
__device__ __forceinline__ void ldsm4(u32 a, u32& r0, u32& r1, u32& r2, u32& r3) {
    asm volatile("ldmatrix.sync.aligned.m8n8.x4.shared.b16 {%0,%1,%2,%3}, [%4];"
        : "=r"(r0), "=r"(r1), "=r"(r2), "=r"(r3) : "r"(a));
}
__device__ __forceinline__ void mmabf(float* d, const u32* a, const u32* b) {
    asm volatile("mma.sync.aligned.m16n8k16.row.col.f32.bf16.bf16.f32 "
        "{%0,%1,%2,%3}, {%4,%5,%6,%7}, {%8,%9}, {%0,%1,%2,%3};"
        : "+f"(d[0]), "+f"(d[1]), "+f"(d[2]), "+f"(d[3])
        : "r"(a[0]), "r"(a[1]), "r"(a[2]), "r"(a[3]), "r"(b[0]), "r"(b[1]));
}
__device__ __forceinline__ void split2(float x, float y, u32& hi, u32& lo) {
    bf hx = __float2bfloat16(x), hy = __float2bfloat16(y);
    bf lx = __float2bfloat16(x - __bfloat162float(hx));
    bf ly = __float2bfloat16(y - __bfloat162float(hy));
    hi = (u32)__bfloat16_as_ushort(hx) | ((u32)__bfloat16_as_ushort(hy) << 16);
    lo = (u32)__bfloat16_as_ushort(lx) | ((u32)__bfloat16_as_ushort(ly) << 16);
}
// fast exp on FMA pipe (rel err ~2e-6)
__device__ __forceinline__ float fexp(float x) {
    float t = x * 1.4426950408889634f;
    float f = t + 12582912.0f;
    int ib = __float_as_int(f);
    float n = f - 12582912.0f;
    float r = t - n;
    float p = 1.3333558e-3f;
    p = fmaf(p, r, 9.6181291e-3f);
    p = fmaf(p, r, 5.5504109e-2f);
    p = fmaf(p, r, 2.4022651e-1f);
    p = fmaf(p, r, 6.9314718e-1f);
    p = fmaf(p, r, 1.0f);
    return p * __int_as_float((ib << 23) + 0x3F800000);
}

__device__ __forceinline__ void ldtile32a(const bf* __restrict__ g, int ldg, u32 s, int rows) {
    for (int i = threadIdx.x; i < rows * 4; i += 256) {
        int r = i >> 2, c = (i & 3) << 3;
        cpa16(s + (u32)((r * LD + c) << 1), g + (size_t)r * ldg + c);
    }
}

// 3-product hi/lo emulation chunk
template<int NF>
__device__ __forceinline__ void mma_chunk(
    float (&acc)[2][NF][4],
    const bf* Ah, const bf* Al, const bf* Bh, const bf* Bl,
    int wm, int wn, int lane)
{
    const u32 ahb = s2u(Ah) + (u32)(wm * 32 * LD * 2);
    const u32 alb = s2u(Al) + (u32)(wm * 32 * LD * 2);
    const u32 bhb = s2u(Bh) + (u32)(wn * NF * 8 * LD * 2);
    const u32 blb = s2u(Bl) + (u32)(wn * NF * 8 * LD * 2);
    const u32 aoff = (u32)(((lane & 15) * LD + ((lane >> 4) << 3)) * 2);
    const u32 boff = (u32)((((lane & 7) + ((lane >> 4) << 3)) * LD + (((lane >> 3) & 1) << 3)) * 2);
    #pragma unroll
    for (int kk = 0; kk < 32; kk += 16) {
        u32 ah[2][4], al[2][4], bhf[NF][2], blf[NF][2];
        #pragma unroll
        for (int i = 0; i < 2; i++) {
            ldsm4(ahb + aoff + kk * 2 + i * 16 * LD * 2, ah[i][0], ah[i][1], ah[i][2], ah[i][3]);
            ldsm4(alb + aoff + kk * 2 + i * 16 * LD * 2, al[i][0], al[i][1], al[i][2], al[i][3]);
        }
        #pragma unroll
        for (int j = 0; j < NF; j += 2) {
            ldsm4(bhb + boff + kk * 2 + j * 8 * LD * 2, bhf[j][0], bhf[j][1], bhf[j+1][0], bhf[j+1][1]);
            ldsm4(blb + boff + kk * 2 + j * 8 * LD * 2, blf[j][0], blf[j][1], blf[j+1][0], blf[j+1][1]);
        }
        #pragma unroll
        for (int i = 0; i < 2; i++)
            #pragma unroll
            for (int j = 0; j < NF; j++) {
                mmabf(acc[i][j], ah[i], bhf[j]);
                mmabf(acc[i][j], ah[i], blf[j]);
                mmabf(acc[i][j], al[i], bhf[j]);
            }
    }
}

// 1-product plain bf16 chunk (pred path)
template<int NF>
__device__ __forceinline__ void mma_chunk1(
    float (&acc)[2][NF][4],
    const bf* A, const bf* B,
    int wm, int wn, int lane)
{
    const u32 ab = s2u(A) + (u32)(wm * 32 * LD * 2);
    const u32 bb = s2u(B) + (u32)(wn * NF * 8 * LD * 2);
    const u32 aoff = (u32)(((lane & 15) * LD + ((lane >> 4) << 3)) * 2);
    const u32 boff = (u32)((((lane & 7) + ((lane >> 4) << 3)) * LD + (((lane >> 3) & 1) << 3)) * 2);
    #pragma unroll
    for (int kk = 0; kk < 32; kk += 16) {
        u32 a[2][4], bfr[NF][2];
        #pragma unroll
        for (int i = 0; i < 2; i++)
            ldsm4(ab + aoff + kk * 2 + i * 16 * LD * 2, a[i][0], a[i][1], a[i][2], a[i][3]);
        #pragma unroll
        for (int j = 0; j < NF; j += 2)
            ldsm4(bb + boff + kk * 2 + j * 8 * LD * 2, bfr[j][0], bfr[j][1], bfr[j+1][0], bfr[j+1][1]);
        #pragma unroll
        for (int i = 0; i < 2; i++)
            #pragma unroll
            for (int j = 0; j < NF; j++)
                mmabf(acc[i][j], a[i], bfr[j]);
    }
}

extern __shared__ __align__(16) char dynsm[];

// ============================================================
__global__ __launch_bounds__(256) void ksplit_all(
    const float* __restrict__ hs, const float* __restrict__ Wq,
    const float* __restrict__ Wk, const float* __restrict__ Wv,
    const float* __restrict__ Wo)
{
    const int y = blockIdx.y;
    const float* src; bf* hi; bf* lo; int n4;
    if (y == 0)      { src = hs; hi = g_Xhi;    lo = g_Xlo;    n4 = 524288; }
    else if (y == 1) { src = Wq; hi = g_Whi[0]; lo = g_Wlo[0]; n4 = 262144; }
    else if (y == 2) { src = Wk; hi = g_Whi[1]; lo = g_Wlo[1]; n4 = 262144; }
    else if (y == 3) { src = Wv; hi = g_Whi[2]; lo = g_Wlo[2]; n4 = 262144; }
    else             { src = Wo; hi = g_Whi[3]; lo = g_Wlo[3]; n4 = 262144; }
    int i = blockIdx.x * 256 + threadIdx.x;
    if (i < n4) {
        float4 v = ((const float4*)src)[i];
        u32 h0, l0, h1, l1;
        split2(v.x, v.y, h0, l0);
        split2(v.z, v.w, h1, l1);
        ((uint2*)hi)[i] = make_uint2(h0, h1);
        ((uint2*)lo)[i] = make_uint2(l0, l1);
    }
}

// ============================================================
// QKV. grid(8n,16m,3z). 2-stage pipeline, 80KB smem, 2 CTAs/SM.
// ============================================================
__global__ __launch_bounds__(256, 2) void qkv_mma(
    const float* __restrict__ bq, const float* __restrict__ bk, const float* __restrict__ bv)
{
    bf* buf = (bf*)dynsm;
    const int tid = threadIdx.x, lane = tid & 31, wid = tid >> 5;
    const int wm = wid & 3, wn = wid >> 2;
    const int g = lane >> 2, ti = lane & 3;
    const int z = blockIdx.z, m0 = blockIdx.y * 128, n0 = blockIdx.x * 128;
    const bf* Whi = g_Whi[z]; const bf* Wlo = g_Wlo[z];
    const float* bias = z == 0 ? bq : (z == 1 ? bk : bv);

    float acc[2][8][4];
    #pragma unroll
    for (int i = 0; i < 2; i++)
        #pragma unroll
        for (int j = 0; j < 8; j++)
            #pragma unroll
            for (int r = 0; r < 4; r++) acc[i][j][r] = 0.f;

    auto issue = [&](int c) {
        bf* p = buf + (c & 1) * 4 * TS;
        const int k0 = c * 32;
        ldtile32a(g_Xhi + (size_t)m0 * 1024 + k0, 1024, s2u(p), 128);
        ldtile32a(g_Xlo + (size_t)m0 * 1024 + k0, 1024, s2u(p + TS), 128);
        ldtile32a(Whi + (size_t)n0 * 1024 + k0, 1024, s2u(p + 2 * TS), 128);
        ldtile32a(Wlo + (size_t)n0 * 1024 + k0, 1024, s2u(p + 3 * TS), 128);
        cpcommit();
    };
    issue(0); issue(1);

    for (int c = 0; c < 32; c++) {
        if (c == 31) cpwait0(); else cpwait1();
        __syncthreads();
        bf* p = buf + (c & 1) * 4 * TS;
        mma_chunk<8>(acc, p, p + TS, p + 2 * TS, p + 3 * TS, wm, wn, lane);
        __syncthreads();
        if (c + 2 < 32) issue(c + 2);
    }

    #pragma unroll
    for (int i = 0; i < 2; i++)
        #pragma unroll
        for (int j = 0; j < 8; j++) {
            const int col = n0 + wn * 64 + j * 8 + ti * 2;
            const int h = col >> 6, d = col & 63;
            const float b0v = bias[col], b1v = bias[col + 1];
            #pragma unroll
            for (int hr = 0; hr < 2; hr++) {
                const int row = m0 + wm * 32 + i * 16 + g + hr * 8;
                const int b_ = row >> 10, s = row & 1023;
                const size_t ob = ((size_t)(b_ * Hh + h) * Ss + s) * 64 + d;
                const float v0 = acc[i][j][hr * 2] + b0v, v1 = acc[i][j][hr * 2 + 1] + b1v;
                u32 h2, l2;
                if (z == 0) {
                    split2(v0 * 0.125f, v1 * 0.125f, h2, l2);
                    *(u32*)&g_qhi[ob] = h2; *(u32*)&g_qlo[ob] = l2;
                } else if (z == 1) {
                    split2(v0, v1, h2, l2);
                    *(u32*)&g_khi[ob] = h2; *(u32*)&g_klo[ob] = l2;
                } else {
                    split2(v0, v1, h2, l2);
                    *(u32*)&g_vhi[ob] = h2; *(u32*)&g_vlo[ob] = l2;
                }
            }
        }
}

// ============================================================
// feature map from split q/k -> bf16 features (hi only), all-fexp
// ============================================================
__global__ __launch_bounds__(256) void feat_kernel(
    const float* __restrict__ Wfq, const float* __restrict__ bfq,
    const float* __restrict__ Wfk, const float* __restrict__ bfk)
{
    const float* Wf; const float* bfp; const bf *sh, *sl; float scale; bf* dh;
    if (blockIdx.y == 0) { Wf = Wfq; bfp = bfq; sh = g_qhi; sl = g_qlo; scale = 8.f; dh = g_fqhi; }
    else                 { Wf = Wfk; bfp = bfk; sh = g_khi; sl = g_klo; scale = 1.f; dh = g_fkhi; }

    __shared__ float Wt[64][65];
    __shared__ float bsm[64];
    __shared__ float qs[4][64];

    const int tid = threadIdx.x;
    #pragma unroll
    for (int p = 0; p < 16; p++) {
        int idx = p * 256 + tid;
        Wt[idx & 63][idx >> 6] = Wf[idx];
    }
    if (tid < 64) bsm[tid] = bfp[tid];

    const int rowbase = blockIdx.x * 128;
    const int e = tid & 63, rr = tid >> 6;

    for (int r0 = 0; r0 < 128; r0 += 4) {
        __syncthreads();
        int row = rowbase + r0 + rr;
        size_t so = (size_t)row * 64 + e;
        qs[rr][e] = (__bfloat162float(sh[so]) + __bfloat162float(sl[so])) * scale;
        __syncthreads();
        float y = bsm[e];
        #pragma unroll
        for (int d = 0; d < 64; d++) y += Wt[d][e] * qs[rr][d];
        float e0 = fexp(y), e1 = fexp(-y);
        size_t o = (size_t)row * 128 + e;
        dh[o]      = __float2bfloat16(e0);
        dh[o + 64] = __float2bfloat16(e1);
    }
}

// ============================================================
// V transpose (plane-wise, bf16): [bh][s][64] -> [bh][64][s]
// ============================================================
__global__ __launch_bounds__(256) void vtrans()
{
    __shared__ bf t[128][72];
    const int bh = blockIdx.x, s0 = blockIdx.y * 128, tid = threadIdx.x;
    #pragma unroll
    for (int a = 0; a < 2; a++) {
        const bf* src = a ? g_vlo : g_vhi;
        bf* dst = a ? g_vtlo : g_vthi;
        __syncthreads();
        for (int i = tid; i < 1024; i += 256) {
            int r = i >> 3, d8 = (i & 7) * 8;
            *(uint4*)&t[r][d8] = *(const uint4*)(src + ((size_t)bh * Ss + s0 + r) * 64 + d8);
        }
        __syncthreads();
        {
            const int d = tid & 63, sg = tid >> 6;
            __align__(16) bf tmp[32];
            #pragma unroll
            for (int s = 0; s < 32; s++) tmp[s] = t[sg * 32 + s][d];
            uint4* dp = (uint4*)(dst + ((size_t)bh * 64 + d) * Ss + s0 + sg * 32);
            #pragma unroll
            for (int q = 0; q < 4; q++) dp[q] = ((uint4*)tmp)[q];
        }
    }
}

// ============================================================
__global__ __launch_bounds__(256) void fksum_kernel()
{
    const int bh = blockIdx.x, tid = threadIdx.x;
    const int e = tid & 127, part = tid >> 7;
    const bf* fh = g_fkhi + (size_t)bh * Ss * 128;
    float s = 0.f;
    for (int r = part; r < 1024; r += 2)
        s += __bfloat162float(fh[(size_t)r * 128 + e]);
    __shared__ float sm[256];
    sm[tid] = s;
    __syncthreads();
    if (tid < 128) g_fks[bh * 128 + tid] = sm[tid] + sm[tid + 128];
}

// ============================================================
// true attention. Q resident (40KB), K 3-stage 64-n tiles (60KB).
// 100KB smem -> 2 CTAs/SM. All-fexp. Rowsum hoisted out of loop.
// ============================================================
__global__ __launch_bounds__(256, 2) void true_mma(float* __restrict__ outT)
{
    bf* qb = (bf*)dynsm;
    bf* kb = (bf*)dynsm + 4 * TS;
    __shared__ float rs[128];
    const int tid = threadIdx.x, lane = tid & 31, wid = tid >> 5;
    const int wm = wid & 3, wn = wid >> 2;
    const int g = lane >> 2, ti = lane & 3;
    const int bh = blockIdx.y, m0 = blockIdx.x * 128;
    float* trow = outT + (size_t)bh * Ss * Ss;
    const bf* qh = g_qhi + ((size_t)bh * Ss + m0) * 64;
    const bf* ql = g_qlo + ((size_t)bh * Ss + m0) * 64;

    if (tid < 128) rs[tid] = 0.f;

    ldtile32a(qh,      64, s2u(qb),          128);
    ldtile32a(ql,      64, s2u(qb + TS),     128);
    ldtile32a(qh + 32, 64, s2u(qb + 2 * TS), 128);
    ldtile32a(ql + 32, 64, s2u(qb + 3 * TS), 128);
    cpcommit();

    auto issueK = [&](int nt) {
        bf* p = kb + (nt % 3) * 4 * HT;
        const bf* kh = g_khi + ((size_t)bh * Ss + nt * 64) * 64;
        const bf* kl = g_klo + ((size_t)bh * Ss + nt * 64) * 64;
        ldtile32a(kh,      64, s2u(p),          64);
        ldtile32a(kl,      64, s2u(p + HT),     64);
        ldtile32a(kh + 32, 64, s2u(p + 2 * HT), 64);
        ldtile32a(kl + 32, 64, s2u(p + 3 * HT), 64);
        cpcommit();
    };
    issueK(0); issueK(1); issueK(2);

    float rsum[4] = {0.f, 0.f, 0.f, 0.f};
    for (int nt = 0; nt < 16; nt++) {
        if (nt <= 13) cpwait2(); else if (nt == 14) cpwait1(); else cpwait0();
        __syncthreads();
        float acc[2][4][4];
        #pragma unroll
        for (int i = 0; i < 2; i++)
            #pragma unroll
            for (int j = 0; j < 4; j++)
                #pragma unroll
                for (int r = 0; r < 4; r++) acc[i][j][r] = 0.f;

        bf* p = kb + (nt % 3) * 4 * HT;
        mma_chunk<4>(acc, qb,          qb + TS,     p,          p + HT,     wm, wn, lane);
        mma_chunk<4>(acc, qb + 2 * TS, qb + 3 * TS, p + 2 * HT, p + 3 * HT, wm, wn, lane);
        __syncthreads();
        if (nt + 3 < 16) issueK(nt + 3);

        const int n0 = nt * 64;
        #pragma unroll
        for (int i = 0; i < 2; i++)
            #pragma unroll
            for (int j = 0; j < 4; j++) {
                float e0 = fexp(acc[i][j][0]), e1 = fexp(acc[i][j][1]);
                float e2 = fexp(acc[i][j][2]), e3 = fexp(acc[i][j][3]);
                rsum[i * 2]     += e0 + e1;
                rsum[i * 2 + 1] += e2 + e3;
                const int col = n0 + wn * 32 + j * 8 + ti * 2;
                const int row = m0 + wm * 32 + i * 16 + g;
                *(float2*)&trow[(size_t)row * 1024 + col]       = make_float2(e0, e1);
                *(float2*)&trow[(size_t)(row + 8) * 1024 + col] = make_float2(e2, e3);
            }
    }

    #pragma unroll
    for (int r = 0; r < 4; r++) {
        float v = rsum[r];
        v += __shfl_xor_sync(0xffffffffu, v, 1);
        v += __shfl_xor_sync(0xffffffffu, v, 2);
        if (ti == 0) atomicAdd(&rs[wm * 32 + (r >> 1) * 16 + (r & 1) * 8 + g], v);
    }
    __syncthreads();
    if (tid < 128) g_inv[bh * Ss + m0 + tid] = 1.f / rs[tid];
}

// ============================================================
// pred: hi-only bf16 features, denom computed in-kernel from smem fq.
// fq resident 40KB, fk 3-stage half-tiles. 100KB smem -> 2 CTAs/SM.
// ============================================================
__global__ __launch_bounds__(256, 2) void pred_mma(float* __restrict__ outP)
{
    bf* fq = (bf*)dynsm;
    bf* kb = (bf*)dynsm + 4 * TS;
    __shared__ float fks_sm[128];
    __shared__ float pinv_sm[128];
    const int tid = threadIdx.x, lane = tid & 31, wid = tid >> 5;
    const int wm = wid & 3, wn = wid >> 2;
    const int g = lane >> 2, ti = lane & 3;
    const int bh = blockIdx.y, m0 = blockIdx.x * 128;
    float* prow = outP + (size_t)bh * Ss * Ss;
    const bf* fqh = g_fqhi + ((size_t)bh * Ss + m0) * 128;

    if (tid < 128) fks_sm[tid] = g_fks[bh * 128 + tid];

    #pragma unroll
    for (int kc = 0; kc < 4; kc++)
        ldtile32a(fqh + kc * 32, 128, s2u(fq + kc * TS), 128);
    cpcommit();

    auto issueFK = [&](int st) {
        bf* p = kb + (st % 3) * 2 * TS;
        const int nt = st >> 1, half = st & 1;
        const bf* kh = g_fkhi + ((size_t)bh * Ss + nt * 128) * 128 + half * 64;
        ldtile32a(kh,      128, s2u(p),      128);
        ldtile32a(kh + 32, 128, s2u(p + TS), 128);
        cpcommit();
    };
    issueFK(0); issueFK(1); issueFK(2);

    float pv[4];
    float acc[2][8][4];
    for (int st = 0; st < 16; st++) {
        const int nt = st >> 1, half = st & 1;
        if (half == 0) {
            #pragma unroll
            for (int i = 0; i < 2; i++)
                #pragma unroll
                for (int j = 0; j < 8; j++)
                    #pragma unroll
                    for (int r = 0; r < 4; r++) acc[i][j][r] = 0.f;
        }
        if (st <= 13) cpwait2(); else if (st == 14) cpwait1(); else cpwait0();
        __syncthreads();

        if (st == 0) {
            if (tid < 128) {
                float d = 0.f;
                #pragma unroll
                for (int kc = 0; kc < 4; kc++) {
                    const bf* fr = fq + kc * TS + tid * LD;
                    #pragma unroll
                    for (int kk = 0; kk < 32; kk++)
                        d += __bfloat162float(fr[kk]) * fks_sm[kc * 32 + kk];
                }
                pinv_sm[tid] = 1.f / d;
            }
            __syncthreads();
            #pragma unroll
            for (int r = 0; r < 4; r++)
                pv[r] = pinv_sm[wm * 32 + (r >> 1) * 16 + (r & 1) * 8 + g];
        }

        bf* p = kb + (st % 3) * 2 * TS;
        const int kc = half * 2;
        mma_chunk1<8>(acc, fq + kc * TS,       p,      wm, wn, lane);
        mma_chunk1<8>(acc, fq + (kc + 1) * TS, p + TS, wm, wn, lane);
        __syncthreads();
        if (st + 3 < 16) issueFK(st + 3);

        if (half == 1) {
            const int n0 = nt * 128;
            #pragma unroll
            for (int i = 0; i < 2; i++)
                #pragma unroll
                for (int j = 0; j < 8; j++) {
                    const int col = n0 + wn * 64 + j * 8 + ti * 2;
                    const int row = m0 + wm * 32 + i * 16 + g;
                    *(float2*)&prow[(size_t)row * 1024 + col] =
                        make_float2(acc[i][j][0] * pv[i * 2], acc[i][j][1] * pv[i * 2]);
                    *(float2*)&prow[(size_t)(row + 8) * 1024 + col] =
                        make_float2(acc[i][j][2] * pv[i * 2 + 1], acc[i][j][3] * pv[i * 2 + 1]);
                }
        }
    }
}

// ============================================================
// ctx = Pnorm @ V (normalize trow in place). 94KB smem, 2 CTAs/SM.
// ============================================================
__global__ __launch_bounds__(256, 2) void ctx_mma(float* __restrict__ outT)
{
    float* tr = (float*)dynsm;
    bf* ab = (bf*)(dynsm + 32768);
    bf* bb = (bf*)(dynsm + 32768 + 2 * TS * 2);
    __shared__ float invsm[128];
    const int tid = threadIdx.x, lane = tid & 31, wid = tid >> 5;
    const int wm = wid & 3, wn = wid >> 2;
    const int g = lane >> 2, ti = lane & 3;
    const int bh = blockIdx.y, m0 = blockIdx.x * 128;
    float* trow = outT + (size_t)bh * Ss * Ss;

    if (tid < 128) invsm[tid] = g_inv[bh * Ss + m0 + tid];

    auto issue = [&](int c) {
        const int st = c & 1;
        u32 ts = s2u(tr + st * 4096);
        for (int i = tid; i < 1024; i += 256) {
            int r = i >> 3, c4 = (i & 7) * 4;
            cpa16(ts + (u32)((r * 32 + c4) * 4), &trow[(size_t)(m0 + r) * 1024 + c * 32 + c4]);
        }
        bf* p = bb + st * 2 * HT;
        ldtile32a(g_vthi + (size_t)bh * 64 * Ss + c * 32, Ss, s2u(p), 64);
        ldtile32a(g_vtlo + (size_t)bh * 64 * Ss + c * 32, Ss, s2u(p + HT), 64);
        cpcommit();
    };
    issue(0); issue(1);

    float acc[2][4][4];
    #pragma unroll
    for (int i = 0; i < 2; i++)
        #pragma unroll
        for (int j = 0; j < 4; j++)
            #pragma unroll
            for (int r = 0; r < 4; r++) acc[i][j][r] = 0.f;

    for (int c = 0; c < 32; c++) {
        if (c == 31) cpwait0(); else cpwait1();
        __syncthreads();
        const int st = c & 1;
        float* trs = tr + st * 4096;
        for (int i = tid; i < 1024; i += 256) {
            int r = i >> 3, c4 = (i & 7) * 4;
            float4 v = *(float4*)&trs[r * 32 + c4];
            float iv = invsm[r];
            v.x *= iv; v.y *= iv; v.z *= iv; v.w *= iv;
            *(float4*)&trow[(size_t)(m0 + r) * 1024 + c * 32 + c4] = v;
            u32 h0, l0, h1, l1;
            split2(v.x, v.y, h0, l0);
            split2(v.z, v.w, h1, l1);
            *(u32*)&ab[r * LD + c4] = h0;      *(u32*)&ab[r * LD + c4 + 2] = h1;
            *(u32*)&ab[TS + r * LD + c4] = l0; *(u32*)&ab[TS + r * LD + c4 + 2] = l1;
        }
        __syncthreads();
        bf* p = bb + st * 2 * HT;
        mma_chunk<4>(acc, ab, ab + TS, p, p + HT, wm, wn, lane);
        __syncthreads();
        if (c + 2 < 32) issue(c + 2);
    }

    #pragma unroll
    for (int i = 0; i < 2; i++)
        #pragma unroll
        for (int j = 0; j < 4; j++) {
            const int col = wn * 32 + j * 8 + ti * 2;
            #pragma unroll
            for (int hr = 0; hr < 2; hr++) {
                const int row = m0 + wm * 32 + i * 16 + g + hr * 8;
                const size_t ob = ((size_t)bh * Ss + row) * 64 + col;
                u32 h2, l2;
                split2(acc[i][j][hr * 2], acc[i][j][hr * 2 + 1], h2, l2);
                *(u32*)&g_chi[ob] = h2; *(u32*)&g_clo[ob] = l2;
            }
        }
}

// ============================================================
// outproj. grid(8n,16m). 3-stage pipeline.
// ============================================================
__global__ __launch_bounds__(256) void outproj_mma(const float* __restrict__ bo, float* __restrict__ out)
{
    bf* buf = (bf*)dynsm;
    const int tid = threadIdx.x, lane = tid & 31, wid = tid >> 5;
    const int wm = wid & 3, wn = wid >> 2;
    const int g = lane >> 2, ti = lane & 3;
    const int m0 = blockIdx.y * 128, n0 = blockIdx.x * 128;
    const int b_ = m0 >> 10, s0 = m0 & 1023;

    float acc[2][8][4];
    #pragma unroll
    for (int i = 0; i < 2; i++)
        #pragma unroll
        for (int j = 0; j < 8; j++)
            #pragma unroll
            for (int r = 0; r < 4; r++) acc[i][j][r] = 0.f;

    auto issue = [&](int c) {
        bf* p = buf + (c % 3) * 4 * TS;
        const int k0 = c * 32;
        const int h = k0 >> 6, doff = k0 & 63;
        const size_t abase = ((size_t)(b_ * Hh + h) * Ss + s0) * 64 + doff;
        ldtile32a(g_chi + abase, 64, s2u(p), 128);
        ldtile32a(g_clo + abase, 64, s2u(p + TS), 128);
        ldtile32a(g_Whi[3] + (size_t)n0 * 1024 + k0, 1024, s2u(p + 2 * TS), 128);
        ldtile32a(g_Wlo[3] + (size_t)n0 * 1024 + k0, 1024, s2u(p + 3 * TS), 128);
        cpcommit();
    };
    issue(0); issue(1); issue(2);

    for (int c = 0; c < 32; c++) {
        if (c <= 29) cpwait2(); else if (c == 30) cpwait1(); else cpwait0();
        __syncthreads();
        bf* p = buf + (c % 3) * 4 * TS;
        mma_chunk<8>(acc, p, p + TS, p + 2 * TS, p + 3 * TS, wm, wn, lane);
        __syncthreads();
        if (c + 3 < 32) issue(c + 3);
    }

    #pragma unroll
    for (int i = 0; i < 2; i++)
        #pragma unroll
        for (int j = 0; j < 8; j++) {
            const int col = n0 + wn * 64 + j * 8 + ti * 2;
            const float b0v = bo[col], b1v = bo[col + 1];
            #pragma unroll
            for (int hr = 0; hr < 2; hr++) {
                const int row = m0 + wm * 32 + i * 16 + g + hr * 8;
                *(float2*)&out[(size_t)row * 1024 + col] =
                    make_float2(acc[i][j][hr * 2] + b0v, acc[i][j][hr * 2 + 1] + b1v);
            }
        }
}

// ============================================================
extern "C" void kernel_launch(void* const* d_in, const int* in_sizes, int n_in,
                              void* d_out, int out_size)
{
    const float* hs  = (const float*)d_in[0];
    const float* Wq  = (const float*)d_in[1];
    const float* bq  = (const float*)d_in[2];
    const float* Wk  = (const float*)d_in[3];
    const float* bk  = (const float*)d_in[4];
    const float* Wv  = (const float*)d_in[5];
    const float* bv  = (const float*)d_in[6];
    const float* Wo  = (const float*)d_in[7];
    const float* bo  = (const float*)d_in[8];
    const float* Wfq = (const float*)d_in[9];
    const float* bfq = (const float*)d_in[10];
    const float* Wfk = (const float*)d_in[11];
    const float* bfk = (const float*)d_in[12];
    float* out = (float*)d_out;

    const int SM_GEMM2 = 8 * TS * 2;                          // 81920 (2 CTA/SM)
    const int SM_GEMM3 = 12 * TS * 2;                         // 122880
    const int SM_TRUE  = 4 * TS * 2 + 12 * HT * 2;            // 102400 (2 CTA/SM)
    const int SM_PRED  = (4 + 6) * TS * 2;                    // 102400 (2 CTA/SM)
    const int SM_CTX   = 32768 + 4 * TS * 2 + 4 * HT * 2;     // 94208  (2 CTA/SM)
    cudaFuncSetAttribute(qkv_mma,     cudaFuncAttributeMaxDynamicSharedMemorySize, SM_GEMM2);
    cudaFuncSetAttribute(true_mma,    cudaFuncAttributeMaxDynamicSharedMemorySize, SM_TRUE);
    cudaFuncSetAttribute(pred_mma,    cudaFuncAttributeMaxDynamicSharedMemorySize, SM_PRED);
    cudaFuncSetAttribute(ctx_mma,     cudaFuncAttributeMaxDynamicSharedMemorySize, SM_CTX);
    cudaFuncSetAttribute(outproj_mma, cudaFuncAttributeMaxDynamicSharedMemorySize, SM_GEMM3);

    cudaStream_t s2;
    cudaStreamCreateWithFlags(&s2, cudaStreamNonBlocking);
    cudaEvent_t evQKV, evVT, evFKS, evJoin;
    cudaEventCreateWithFlags(&evQKV, cudaEventDisableTiming);
    cudaEventCreateWithFlags(&evVT,  cudaEventDisableTiming);
    cudaEventCreateWithFlags(&evFKS, cudaEventDisableTiming);
    cudaEventCreateWithFlags(&evJoin, cudaEventDisableTiming);

    ksplit_all<<<dim3(2048, 5), 256>>>(hs, Wq, Wk, Wv, Wo);
    qkv_mma<<<dim3(8, 16, 3), 256, SM_GEMM2>>>(bq, bk, bv);
    cudaEventRecord(evQKV, 0);

    // side stream: vtrans (needs only V from qkv), then pred after fksum
    cudaStreamWaitEvent(s2, evQKV, 0);
    vtrans<<<dim3(32, 8), 256, 0, s2>>>();
    cudaEventRecord(evVT, s2);

    // main: feat -> fksum
    feat_kernel<<<dim3(256, 2), 256>>>(Wfq, bfq, Wfk, bfk);
    fksum_kernel<<<32, 256>>>();
    cudaEventRecord(evFKS, 0);

    // side stream: pred (needs fkhi + fksum)
    cudaStreamWaitEvent(s2, evFKS, 0);
    pred_mma<<<dim3(8, 32), 256, SM_PRED, s2>>>(out + OFF_PRED);
    cudaEventRecord(evJoin, s2);

    // main chain: true (needs q/k only), ctx (needs vt -> wait evVT), outproj
    true_mma<<<dim3(8, 32), 256, SM_TRUE>>>(out + OFF_TRUE);
    cudaStreamWaitEvent(0, evVT, 0);
    ctx_mma<<<dim3(8, 32), 256, SM_CTX>>>(out + OFF_TRUE);
    outproj_mma<<<dim3(8, 16), 256, SM_GEMM3>>>(bo, out);

    cudaStreamWaitEvent(0, evJoin, 0);
}

// round 16
// speedup vs baseline: 1.1730x; 1.0996x over previous
#include <cuda_runtime.h>
#include <cuda_bf16.h>
#include <math.h>
#include <stdint.h>

#define Ss 1024
#define Hh 16
#define BH 32
#define LD 40
typedef __nv_bfloat16 bf;
typedef unsigned int u32;

#define OFF_PRED (2048*1024)
#define OFF_TRUE (OFF_PRED + 32*1024*1024)
#define TS (128*LD)
#define HT (64*LD)

// ---------------- scratch ----------------
__device__ bf g_qhi[BH*Ss*64], g_qlo[BH*Ss*64];     // prescaled by 1/8
__device__ bf g_khi[BH*Ss*64], g_klo[BH*Ss*64];
__device__ bf g_vhi[BH*Ss*64], g_vlo[BH*Ss*64];     // [bh][s][d]
__device__ bf g_vthi[BH*64*Ss], g_vtlo[BH*64*Ss];   // [bh][d][s]
__device__ bf g_Xhi[2048*1024], g_Xlo[2048*1024];
__device__ bf g_Whi[4][1024*1024], g_Wlo[4][1024*1024];
__device__ bf g_Wfhi[2][64*64], g_Wflo[2][64*64];   // hedgehog weights split
__device__ bf g_fqhi[BH*Ss*128];                    // bf16 features (hi only)
__device__ bf g_fkhi[BH*Ss*128];
__device__ bf g_chi[BH*Ss*64], g_clo[BH*Ss*64];
__device__ float g_fks[BH*128], g_inv[BH*Ss];

// ---------------- helpers ----------------
__device__ __forceinline__ u32 s2u(const void* p) {
    u32 r; asm("{ .reg .u64 t; cvta.to.shared.u64 t, %1; cvt.u32.u64 %0, t; }" : "=r"(r) : "l"(p)); return r;
}
__device__ __forceinline__ void cpa16(u32 dst, const void* src) {
    asm volatile("cp.async.cg.shared.global [%0], [%1], 16;" :: "r"(dst), "l"(src));
}
__device__ __forceinline__ void cpcommit() { asm volatile("cp.async.commit_group;" ::: "memory"); }
__device__ __forceinline__ void cpwait0() { asm volatile("cp.async.wait_group 0;" ::: "memory"); }
__device__ __forceinline__ void cpwait1() { asm volatile("cp.async.wait_group 1;" ::: "memory"); }
__device__ __forceinline__ void cpwait2() { asm volatile("cp.async.wait_group 2;" ::: "memory"); }
__device__ __forceinline__ void ldsm4(u32 a, u32& r0, u32& r1, u32& r2, u32& r3) {
    asm volatile("ldmatrix.sync.aligned.m8n8.x4.shared.b16 {%0,%1,%2,%3}, [%4];"
        : "=r"(r0), "=r"(r1), "=r"(r2), "=r"(r3) : "r"(a));
}
__device__ __forceinline__ void mmabf(float* d, const u32* a, const u32* b) {
    asm volatile("mma.sync.aligned.m16n8k16.row.col.f32.bf16.bf16.f32 "
        "{%0,%1,%2,%3}, {%4,%5,%6,%7}, {%8,%9}, {%0,%1,%2,%3};"
        : "+f"(d[0]), "+f"(d[1]), "+f"(d[2]), "+f"(d[3])
        : "r"(a[0]), "r"(a[1]), "r"(a[2]), "r"(a[3]), "r"(b[0]), "r"(b[1]));
}
__device__ __forceinline__ void split2(float x, float y, u32& hi, u32& lo) {
    bf hx = __float2bfloat16(x), hy = __float2bfloat16(y);
    bf lx = __float2bfloat16(x - __bfloat162float(hx));
    bf ly = __float2bfloat16(y - __bfloat162float(hy));
    hi = (u32)__bfloat16_as_ushort(hx) | ((u32)__bfloat16_as_ushort(hy) << 16);
    lo = (u32)__bfloat16_as_ushort(lx) | ((u32)__bfloat16_as_ushort(ly) << 16);
}
__device__ __forceinline__ u32 packbf(float x, float y) {
    return (u32)__bfloat16_as_ushort(__float2bfloat16(x)) |
           ((u32)__bfloat16_as_ushort(__float2bfloat16(y)) << 16);
}
// fast exp on FMA pipe (rel err ~2e-6)
__device__ __forceinline__ float fexp(float x) {
    float t = x * 1.4426950408889634f;
    float f = t + 12582912.0f;
    int ib = __float_as_int(f);
    float n = f - 12582912.0f;
    float r = t - n;
    float p = 1.3333558e-3f;
    p = fmaf(p, r, 9.6181291e-3f);
    p = fmaf(p, r, 5.5504109e-2f);
    p = fmaf(p, r, 2.4022651e-1f);
    p = fmaf(p, r, 6.9314718e-1f);
    p = fmaf(p, r, 1.0f);
    return p * __int_as_float((ib << 23) + 0x3F800000);
}

__device__ __forceinline__ void ldtile32a(const bf* __restrict__ g, int ldg, u32 s, int rows) {
    for (int i = threadIdx.x; i < rows * 4; i += 256) {
        int r = i >> 2, c = (i & 3) << 3;
        cpa16(s + (u32)((r * LD + c) << 1), g + (size_t)r * ldg + c);
    }
}

// 3-product hi/lo emulation chunk
template<int NF>
__device__ __forceinline__ void mma_chunk(
    float (&acc)[2][NF][4],
    const bf* Ah, const bf* Al, const bf* Bh, const bf* Bl,
    int wm, int wn, int lane)
{
    const u32 ahb = s2u(Ah) + (u32)(wm * 32 * LD * 2);
    const u32 alb = s2u(Al) + (u32)(wm * 32 * LD * 2);
    const u32 bhb = s2u(Bh) + (u32)(wn * NF * 8 * LD * 2);
    const u32 blb = s2u(Bl) + (u32)(wn * NF * 8 * LD * 2);
    const u32 aoff = (u32)(((lane & 15) * LD + ((lane >> 4) << 3)) * 2);
    const u32 boff = (u32)((((lane & 7) + ((lane >> 4) << 3)) * LD + (((lane >> 3) & 1) << 3)) * 2);
    #pragma unroll
    for (int kk = 0; kk < 32; kk += 16) {
        u32 ah[2][4], al[2][4], bhf[NF][2], blf[NF][2];
        #pragma unroll
        for (int i = 0; i < 2; i++) {
            ldsm4(ahb + aoff + kk * 2 + i * 16 * LD * 2, ah[i][0], ah[i][1], ah[i][2], ah[i][3]);
            ldsm4(alb + aoff + kk * 2 + i * 16 * LD * 2, al[i][0], al[i][1], al[i][2], al[i][3]);
        }
        #pragma unroll
        for (int j = 0; j < NF; j += 2) {
            ldsm4(bhb + boff + kk * 2 + j * 8 * LD * 2, bhf[j][0], bhf[j][1], bhf[j+1][0], bhf[j+1][1]);
            ldsm4(blb + boff + kk * 2 + j * 8 * LD * 2, blf[j][0], blf[j][1], blf[j+1][0], blf[j+1][1]);
        }
        #pragma unroll
        for (int i = 0; i < 2; i++)
            #pragma unroll
            for (int j = 0; j < NF; j++) {
                mmabf(acc[i][j], ah[i], bhf[j]);
                mmabf(acc[i][j], ah[i], blf[j]);
                mmabf(acc[i][j], al[i], bhf[j]);
            }
    }
}

// 1-product plain bf16 chunk (pred path)
template<int NF>
__device__ __forceinline__ void mma_chunk1(
    float (&acc)[2][NF][4],
    const bf* A, const bf* B,
    int wm, int wn, int lane)
{
    const u32 ab = s2u(A) + (u32)(wm * 32 * LD * 2);
    const u32 bb = s2u(B) + (u32)(wn * NF * 8 * LD * 2);
    const u32 aoff = (u32)(((lane & 15) * LD + ((lane >> 4) << 3)) * 2);
    const u32 boff = (u32)((((lane & 7) + ((lane >> 4) << 3)) * LD + (((lane >> 3) & 1) << 3)) * 2);
    #pragma unroll
    for (int kk = 0; kk < 32; kk += 16) {
        u32 a[2][4], bfr[NF][2];
        #pragma unroll
        for (int i = 0; i < 2; i++)
            ldsm4(ab + aoff + kk * 2 + i * 16 * LD * 2, a[i][0], a[i][1], a[i][2], a[i][3]);
        #pragma unroll
        for (int j = 0; j < NF; j += 2)
            ldsm4(bb + boff + kk * 2 + j * 8 * LD * 2, bfr[j][0], bfr[j][1], bfr[j+1][0], bfr[j+1][1]);
        #pragma unroll
        for (int i = 0; i < 2; i++)
            #pragma unroll
            for (int j = 0; j < NF; j++)
                mmabf(acc[i][j], a[i], bfr[j]);
    }
}

extern __shared__ __align__(16) char dynsm[];

// ============================================================
__global__ __launch_bounds__(256) void ksplit_all(
    const float* __restrict__ hs, const float* __restrict__ Wq,
    const float* __restrict__ Wk, const float* __restrict__ Wv,
    const float* __restrict__ Wo, const float* __restrict__ Wfq,
    const float* __restrict__ Wfk)
{
    const int y = blockIdx.y;
    const float* src; bf* hi; bf* lo; int n4;
    if (y == 0)      { src = hs;  hi = g_Xhi;     lo = g_Xlo;     n4 = 524288; }
    else if (y == 1) { src = Wq;  hi = g_Whi[0];  lo = g_Wlo[0];  n4 = 262144; }
    else if (y == 2) { src = Wk;  hi = g_Whi[1];  lo = g_Wlo[1];  n4 = 262144; }
    else if (y == 3) { src = Wv;  hi = g_Whi[2];  lo = g_Wlo[2];  n4 = 262144; }
    else if (y == 4) { src = Wo;  hi = g_Whi[3];  lo = g_Wlo[3];  n4 = 262144; }
    else if (y == 5) { src = Wfq; hi = g_Wfhi[0]; lo = g_Wflo[0]; n4 = 1024; }
    else             { src = Wfk; hi = g_Wfhi[1]; lo = g_Wflo[1]; n4 = 1024; }
    int i = blockIdx.x * 256 + threadIdx.x;
    if (i < n4) {
        float4 v = ((const float4*)src)[i];
        u32 h0, l0, h1, l1;
        split2(v.x, v.y, h0, l0);
        split2(v.z, v.w, h1, l1);
        ((uint2*)hi)[i] = make_uint2(h0, h1);
        ((uint2*)lo)[i] = make_uint2(l0, l1);
    }
}

// ============================================================
// QKV. grid(8n,16m,3z). 2-stage pipeline, 80KB smem, 2 CTAs/SM.
// ============================================================
__global__ __launch_bounds__(256, 2) void qkv_mma(
    const float* __restrict__ bq, const float* __restrict__ bk, const float* __restrict__ bv)
{
    bf* buf = (bf*)dynsm;
    const int tid = threadIdx.x, lane = tid & 31, wid = tid >> 5;
    const int wm = wid & 3, wn = wid >> 2;
    const int g = lane >> 2, ti = lane & 3;
    const int z = blockIdx.z, m0 = blockIdx.y * 128, n0 = blockIdx.x * 128;
    const bf* Whi = g_Whi[z]; const bf* Wlo = g_Wlo[z];
    const float* bias = z == 0 ? bq : (z == 1 ? bk : bv);

    float acc[2][8][4];
    #pragma unroll
    for (int i = 0; i < 2; i++)
        #pragma unroll
        for (int j = 0; j < 8; j++)
            #pragma unroll
            for (int r = 0; r < 4; r++) acc[i][j][r] = 0.f;

    auto issue = [&](int c) {
        bf* p = buf + (c & 1) * 4 * TS;
        const int k0 = c * 32;
        ldtile32a(g_Xhi + (size_t)m0 * 1024 + k0, 1024, s2u(p), 128);
        ldtile32a(g_Xlo + (size_t)m0 * 1024 + k0, 1024, s2u(p + TS), 128);
        ldtile32a(Whi + (size_t)n0 * 1024 + k0, 1024, s2u(p + 2 * TS), 128);
        ldtile32a(Wlo + (size_t)n0 * 1024 + k0, 1024, s2u(p + 3 * TS), 128);
        cpcommit();
    };
    issue(0); issue(1);

    for (int c = 0; c < 32; c++) {
        if (c == 31) cpwait0(); else cpwait1();
        __syncthreads();
        bf* p = buf + (c & 1) * 4 * TS;
        mma_chunk<8>(acc, p, p + TS, p + 2 * TS, p + 3 * TS, wm, wn, lane);
        __syncthreads();
        if (c + 2 < 32) issue(c + 2);
    }

    #pragma unroll
    for (int i = 0; i < 2; i++)
        #pragma unroll
        for (int j = 0; j < 8; j++) {
            const int col = n0 + wn * 64 + j * 8 + ti * 2;
            const int h = col >> 6, d = col & 63;
            const float b0v = bias[col], b1v = bias[col + 1];
            #pragma unroll
            for (int hr = 0; hr < 2; hr++) {
                const int row = m0 + wm * 32 + i * 16 + g + hr * 8;
                const int b_ = row >> 10, s = row & 1023;
                const size_t ob = ((size_t)(b_ * Hh + h) * Ss + s) * 64 + d;
                const float v0 = acc[i][j][hr * 2] + b0v, v1 = acc[i][j][hr * 2 + 1] + b1v;
                u32 h2, l2;
                if (z == 0) {
                    split2(v0 * 0.125f, v1 * 0.125f, h2, l2);
                    *(u32*)&g_qhi[ob] = h2; *(u32*)&g_qlo[ob] = l2;
                } else if (z == 1) {
                    split2(v0, v1, h2, l2);
                    *(u32*)&g_khi[ob] = h2; *(u32*)&g_klo[ob] = l2;
                } else {
                    split2(v0, v1, h2, l2);
                    *(u32*)&g_vhi[ob] = h2; *(u32*)&g_vlo[ob] = l2;
                }
            }
        }
}

// ============================================================
// feature map as MMA: y = x @ Wf^T + b ; f = [fexp(y), fexp(-y)].
// A = q/k split planes (128-row tile), B = Wf split (resident).
// 60KB smem, 2 CTAs/SM. grid(256 mtiles, 2 qk).
// ============================================================
__global__ __launch_bounds__(256, 2) void feat_mma(
    const float* __restrict__ bfq, const float* __restrict__ bfk)
{
    bf* ab = (bf*)dynsm;             // 4*TS: Ah c0, Al c0, Ah c1, Al c1
    bf* bb = (bf*)dynsm + 4 * TS;    // 4*HT: Bh c0, Bl c0, Bh c1, Bl c1
    const int tid = threadIdx.x, lane = tid & 31, wid = tid >> 5;
    const int wm = wid & 3, wn = wid >> 2;
    const int g = lane >> 2, ti = lane & 3;
    const int qk = blockIdx.y;
    const size_t m0 = (size_t)blockIdx.x * 128;
    const bf* sh = qk ? g_khi : g_qhi;
    const bf* sl = qk ? g_klo : g_qlo;
    const bf* wh = g_Wfhi[qk];
    const bf* wl = g_Wflo[qk];
    const float* bias = qk ? bfk : bfq;
    const float scale = qk ? 1.f : 8.f;
    bf* dh = qk ? g_fkhi : g_fqhi;

    ldtile32a(sh + m0 * 64,      64, s2u(ab),          128);
    ldtile32a(sl + m0 * 64,      64, s2u(ab + TS),     128);
    ldtile32a(sh + m0 * 64 + 32, 64, s2u(ab + 2 * TS), 128);
    ldtile32a(sl + m0 * 64 + 32, 64, s2u(ab + 3 * TS), 128);
    ldtile32a(wh,      64, s2u(bb),          64);
    ldtile32a(wl,      64, s2u(bb + HT),     64);
    ldtile32a(wh + 32, 64, s2u(bb + 2 * HT), 64);
    ldtile32a(wl + 32, 64, s2u(bb + 3 * HT), 64);
    cpcommit();
    cpwait0();
    __syncthreads();

    float acc[2][4][4];
    #pragma unroll
    for (int i = 0; i < 2; i++)
        #pragma unroll
        for (int j = 0; j < 4; j++)
            #pragma unroll
            for (int r = 0; r < 4; r++) acc[i][j][r] = 0.f;

    mma_chunk<4>(acc, ab,          ab + TS,     bb,          bb + HT,     wm, wn, lane);
    mma_chunk<4>(acc, ab + 2 * TS, ab + 3 * TS, bb + 2 * HT, bb + 3 * HT, wm, wn, lane);

    #pragma unroll
    for (int i = 0; i < 2; i++)
        #pragma unroll
        for (int j = 0; j < 4; j++) {
            const int col = wn * 32 + j * 8 + ti * 2;
            const float b0v = bias[col], b1v = bias[col + 1];
            #pragma unroll
            for (int hr = 0; hr < 2; hr++) {
                const size_t row = m0 + wm * 32 + i * 16 + g + hr * 8;
                const float y0 = acc[i][j][hr * 2] * scale + b0v;
                const float y1 = acc[i][j][hr * 2 + 1] * scale + b1v;
                *(u32*)&dh[row * 128 + col]      = packbf(fexp(y0), fexp(y1));
                *(u32*)&dh[row * 128 + 64 + col] = packbf(fexp(-y0), fexp(-y1));
            }
        }
}

// ============================================================
// V transpose (plane-wise, bf16): [bh][s][64] -> [bh][64][s]
// ============================================================
__global__ __launch_bounds__(256) void vtrans()
{
    __shared__ bf t[128][72];
    const int bh = blockIdx.x, s0 = blockIdx.y * 128, tid = threadIdx.x;
    #pragma unroll
    for (int a = 0; a < 2; a++) {
        const bf* src = a ? g_vlo : g_vhi;
        bf* dst = a ? g_vtlo : g_vthi;
        __syncthreads();
        for (int i = tid; i < 1024; i += 256) {
            int r = i >> 3, d8 = (i & 7) * 8;
            *(uint4*)&t[r][d8] = *(const uint4*)(src + ((size_t)bh * Ss + s0 + r) * 64 + d8);
        }
        __syncthreads();
        {
            const int d = tid & 63, sg = tid >> 6;
            __align__(16) bf tmp[32];
            #pragma unroll
            for (int s = 0; s < 32; s++) tmp[s] = t[sg * 32 + s][d];
            uint4* dp = (uint4*)(dst + ((size_t)bh * 64 + d) * Ss + s0 + sg * 32);
            #pragma unroll
            for (int q = 0; q < 4; q++) dp[q] = ((uint4*)tmp)[q];
        }
    }
}

// ============================================================
__global__ __launch_bounds__(256) void fksum_kernel()
{
    const int bh = blockIdx.x, tid = threadIdx.x;
    const int e = tid & 127, part = tid >> 7;
    const bf* fh = g_fkhi + (size_t)bh * Ss * 128;
    float s = 0.f;
    for (int r = part; r < 1024; r += 2)
        s += __bfloat162float(fh[(size_t)r * 128 + e]);
    __shared__ float sm[256];
    sm[tid] = s;
    __syncthreads();
    if (tid < 128) g_fks[bh * 128 + tid] = sm[tid] + sm[tid + 128];
}

// ============================================================
// true attention. Q resident (40KB), K 3-stage 64-n tiles (60KB).
// 100KB smem -> 2 CTAs/SM. All-fexp. Rowsum hoisted out of loop.
// ============================================================
__global__ __launch_bounds__(256, 2) void true_mma(float* __restrict__ outT)
{
    bf* qb = (bf*)dynsm;
    bf* kb = (bf*)dynsm + 4 * TS;
    __shared__ float rs[128];
    const int tid = threadIdx.x, lane = tid & 31, wid = tid >> 5;
    const int wm = wid & 3, wn = wid >> 2;
    const int g = lane >> 2, ti = lane & 3;
    const int bh = blockIdx.y, m0 = blockIdx.x * 128;
    float* trow = outT + (size_t)bh * Ss * Ss;
    const bf* qh = g_qhi + ((size_t)bh * Ss + m0) * 64;
    const bf* ql = g_qlo + ((size_t)bh * Ss + m0) * 64;

    if (tid < 128) rs[tid] = 0.f;

    ldtile32a(qh,      64, s2u(qb),          128);
    ldtile32a(ql,      64, s2u(qb + TS),     128);
    ldtile32a(qh + 32, 64, s2u(qb + 2 * TS), 128);
    ldtile32a(ql + 32, 64, s2u(qb + 3 * TS), 128);
    cpcommit();

    auto issueK = [&](int nt) {
        bf* p = kb + (nt % 3) * 4 * HT;
        const bf* kh = g_khi + ((size_t)bh * Ss + nt * 64) * 64;
        const bf* kl = g_klo + ((size_t)bh * Ss + nt * 64) * 64;
        ldtile32a(kh,      64, s2u(p),          64);
        ldtile32a(kl,      64, s2u(p + HT),     64);
        ldtile32a(kh + 32, 64, s2u(p + 2 * HT), 64);
        ldtile32a(kl + 32, 64, s2u(p + 3 * HT), 64);
        cpcommit();
    };
    issueK(0); issueK(1); issueK(2);

    float rsum[4] = {0.f, 0.f, 0.f, 0.f};
    for (int nt = 0; nt < 16; nt++) {
        if (nt <= 13) cpwait2(); else if (nt == 14) cpwait1(); else cpwait0();
        __syncthreads();
        float acc[2][4][4];
        #pragma unroll
        for (int i = 0; i < 2; i++)
            #pragma unroll
            for (int j = 0; j < 4; j++)
                #pragma unroll
                for (int r = 0; r < 4; r++) acc[i][j][r] = 0.f;

        bf* p = kb + (nt % 3) * 4 * HT;
        mma_chunk<4>(acc, qb,          qb + TS,     p,          p + HT,     wm, wn, lane);
        mma_chunk<4>(acc, qb + 2 * TS, qb + 3 * TS, p + 2 * HT, p + 3 * HT, wm, wn, lane);
        __syncthreads();
        if (nt + 3 < 16) issueK(nt + 3);

        const int n0 = nt * 64;
        #pragma unroll
        for (int i = 0; i < 2; i++)
            #pragma unroll
            for (int j = 0; j < 4; j++) {
                float e0 = fexp(acc[i][j][0]), e1 = fexp(acc[i][j][1]);
                float e2 = fexp(acc[i][j][2]), e3 = fexp(acc[i][j][3]);
                rsum[i * 2]     += e0 + e1;
                rsum[i * 2 + 1] += e2 + e3;
                const int col = n0 + wn * 32 + j * 8 + ti * 2;
                const int row = m0 + wm * 32 + i * 16 + g;
                *(float2*)&trow[(size_t)row * 1024 + col]       = make_float2(e0, e1);
                *(float2*)&trow[(size_t)(row + 8) * 1024 + col] = make_float2(e2, e3);
            }
    }

    #pragma unroll
    for (int r = 0; r < 4; r++) {
        float v = rsum[r];
        v += __shfl_xor_sync(0xffffffffu, v, 1);
        v += __shfl_xor_sync(0xffffffffu, v, 2);
        if (ti == 0) atomicAdd(&rs[wm * 32 + (r >> 1) * 16 + (r & 1) * 8 + g], v);
    }
    __syncthreads();
    if (tid < 128) g_inv[bh * Ss + m0 + tid] = 1.f / rs[tid];
}

// ============================================================
// pred: hi-only bf16 features, denom computed in-kernel from smem fq.
// fq resident 40KB, fk 3-stage half-tiles. 100KB smem -> 2 CTAs/SM.
// ============================================================
__global__ __launch_bounds__(256, 2) void pred_mma(float* __restrict__ outP)
{
    bf* fq = (bf*)dynsm;
    bf* kb = (bf*)dynsm + 4 * TS;
    __shared__ float fks_sm[128];
    __shared__ float pinv_sm[128];
    const int tid = threadIdx.x, lane = tid & 31, wid = tid >> 5;
    const int wm = wid & 3, wn = wid >> 2;
    const int g = lane >> 2, ti = lane & 3;
    const int bh = blockIdx.y, m0 = blockIdx.x * 128;
    float* prow = outP + (size_t)bh * Ss * Ss;
    const bf* fqh = g_fqhi + ((size_t)bh * Ss + m0) * 128;

    if (tid < 128) fks_sm[tid] = g_fks[bh * 128 + tid];

    #pragma unroll
    for (int kc = 0; kc < 4; kc++)
        ldtile32a(fqh + kc * 32, 128, s2u(fq + kc * TS), 128);
    cpcommit();

    auto issueFK = [&](int st) {
        bf* p = kb + (st % 3) * 2 * TS;
        const int nt = st >> 1, half = st & 1;
        const bf* kh = g_fkhi + ((size_t)bh * Ss + nt * 128) * 128 + half * 64;
        ldtile32a(kh,      128, s2u(p),      128);
        ldtile32a(kh + 32, 128, s2u(p + TS), 128);
        cpcommit();
    };
    issueFK(0); issueFK(1); issueFK(2);

    float pv[4];
    float acc[2][8][4];
    for (int st = 0; st < 16; st++) {
        const int nt = st >> 1, half = st & 1;
        if (half == 0) {
            #pragma unroll
            for (int i = 0; i < 2; i++)
                #pragma unroll
                for (int j = 0; j < 8; j++)
                    #pragma unroll
                    for (int r = 0; r < 4; r++) acc[i][j][r] = 0.f;
        }
        if (st <= 13) cpwait2(); else if (st == 14) cpwait1(); else cpwait0();
        __syncthreads();

        if (st == 0) {
            if (tid < 128) {
                float d = 0.f;
                #pragma unroll
                for (int kc = 0; kc < 4; kc++) {
                    const bf* fr = fq + kc * TS + tid * LD;
                    #pragma unroll
                    for (int kk = 0; kk < 32; kk++)
                        d += __bfloat162float(fr[kk]) * fks_sm[kc * 32 + kk];
                }
                pinv_sm[tid] = 1.f / d;
            }
            __syncthreads();
            #pragma unroll
            for (int r = 0; r < 4; r++)
                pv[r] = pinv_sm[wm * 32 + (r >> 1) * 16 + (r & 1) * 8 + g];
        }

        bf* p = kb + (st % 3) * 2 * TS;
        const int kc = half * 2;
        mma_chunk1<8>(acc, fq + kc * TS,       p,      wm, wn, lane);
        mma_chunk1<8>(acc, fq + (kc + 1) * TS, p + TS, wm, wn, lane);
        __syncthreads();
        if (st + 3 < 16) issueFK(st + 3);

        if (half == 1) {
            const int n0 = nt * 128;
            #pragma unroll
            for (int i = 0; i < 2; i++)
                #pragma unroll
                for (int j = 0; j < 8; j++) {
                    const int col = n0 + wn * 64 + j * 8 + ti * 2;
                    const int row = m0 + wm * 32 + i * 16 + g;
                    *(float2*)&prow[(size_t)row * 1024 + col] =
                        make_float2(acc[i][j][0] * pv[i * 2], acc[i][j][1] * pv[i * 2]);
                    *(float2*)&prow[(size_t)(row + 8) * 1024 + col] =
                        make_float2(acc[i][j][2] * pv[i * 2 + 1], acc[i][j][3] * pv[i * 2 + 1]);
                }
        }
    }
}

// ============================================================
// ctx = Pnorm @ V (normalize trow in place). 94KB smem, 2 CTAs/SM.
// ============================================================
__global__ __launch_bounds__(256, 2) void ctx_mma(float* __restrict__ outT)
{
    float* tr = (float*)dynsm;
    bf* ab = (bf*)(dynsm + 32768);
    bf* bb = (bf*)(dynsm + 32768 + 2 * TS * 2);
    __shared__ float invsm[128];
    const int tid = threadIdx.x, lane = tid & 31, wid = tid >> 5;
    const int wm = wid & 3, wn = wid >> 2;
    const int g = lane >> 2, ti = lane & 3;
    const int bh = blockIdx.y, m0 = blockIdx.x * 128;
    float* trow = outT + (size_t)bh * Ss * Ss;

    if (tid < 128) invsm[tid] = g_inv[bh * Ss + m0 + tid];

    auto issue = [&](int c) {
        const int st = c & 1;
        u32 ts = s2u(tr + st * 4096);
        for (int i = tid; i < 1024; i += 256) {
            int r = i >> 3, c4 = (i & 7) * 4;
            cpa16(ts + (u32)((r * 32 + c4) * 4), &trow[(size_t)(m0 + r) * 1024 + c * 32 + c4]);
        }
        bf* p = bb + st * 2 * HT;
        ldtile32a(g_vthi + (size_t)bh * 64 * Ss + c * 32, Ss, s2u(p), 64);
        ldtile32a(g_vtlo + (size_t)bh * 64 * Ss + c * 32, Ss, s2u(p + HT), 64);
        cpcommit();
    };
    issue(0); issue(1);

    float acc[2][4][4];
    #pragma unroll
    for (int i = 0; i < 2; i++)
        #pragma unroll
        for (int j = 0; j < 4; j++)
            #pragma unroll
            for (int r = 0; r < 4; r++) acc[i][j][r] = 0.f;

    for (int c = 0; c < 32; c++) {
        if (c == 31) cpwait0(); else cpwait1();
        __syncthreads();
        const int st = c & 1;
        float* trs = tr + st * 4096;
        for (int i = tid; i < 1024; i += 256) {
            int r = i >> 3, c4 = (i & 7) * 4;
            float4 v = *(float4*)&trs[r * 32 + c4];
            float iv = invsm[r];
            v.x *= iv; v.y *= iv; v.z *= iv; v.w *= iv;
            *(float4*)&trow[(size_t)(m0 + r) * 1024 + c * 32 + c4] = v;
            u32 h0, l0, h1, l1;
            split2(v.x, v.y, h0, l0);
            split2(v.z, v.w, h1, l1);
            *(u32*)&ab[r * LD + c4] = h0;      *(u32*)&ab[r * LD + c4 + 2] = h1;
            *(u32*)&ab[TS + r * LD + c4] = l0; *(u32*)&ab[TS + r * LD + c4 + 2] = l1;
        }
        __syncthreads();
        bf* p = bb + st * 2 * HT;
        mma_chunk<4>(acc, ab, ab + TS, p, p + HT, wm, wn, lane);
        __syncthreads();
        if (c + 2 < 32) issue(c + 2);
    }

    #pragma unroll
    for (int i = 0; i < 2; i++)
        #pragma unroll
        for (int j = 0; j < 4; j++) {
            const int col = wn * 32 + j * 8 + ti * 2;
            #pragma unroll
            for (int hr = 0; hr < 2; hr++) {
                const int row = m0 + wm * 32 + i * 16 + g + hr * 8;
                const size_t ob = ((size_t)bh * Ss + row) * 64 + col;
                u32 h2, l2;
                split2(acc[i][j][hr * 2], acc[i][j][hr * 2 + 1], h2, l2);
                *(u32*)&g_chi[ob] = h2; *(u32*)&g_clo[ob] = l2;
            }
        }
}

// ============================================================
// outproj. grid(8n,16m). 3-stage pipeline.
// ============================================================
__global__ __launch_bounds__(256) void outproj_mma(const float* __restrict__ bo, float* __restrict__ out)
{
    bf* buf = (bf*)dynsm;
    const int tid = threadIdx.x, lane = tid & 31, wid = tid >> 5;
    const int wm = wid & 3, wn = wid >> 2;
    const int g = lane >> 2, ti = lane & 3;
    const int m0 = blockIdx.y * 128, n0 = blockIdx.x * 128;
    const int b_ = m0 >> 10, s0 = m0 & 1023;

    float acc[2][8][4];
    #pragma unroll
    for (int i = 0; i < 2; i++)
        #pragma unroll
        for (int j = 0; j < 8; j++)
            #pragma unroll
            for (int r = 0; r < 4; r++) acc[i][j][r] = 0.f;

    auto issue = [&](int c) {
        bf* p = buf + (c % 3) * 4 * TS;
        const int k0 = c * 32;
        const int h = k0 >> 6, doff = k0 & 63;
        const size_t abase = ((size_t)(b_ * Hh + h) * Ss + s0) * 64 + doff;
        ldtile32a(g_chi + abase, 64, s2u(p), 128);
        ldtile32a(g_clo + abase, 64, s2u(p + TS), 128);
        ldtile32a(g_Whi[3] + (size_t)n0 * 1024 + k0, 1024, s2u(p + 2 * TS), 128);
        ldtile32a(g_Wlo[3] + (size_t)n0 * 1024 + k0, 1024, s2u(p + 3 * TS), 128);
        cpcommit();
    };
    issue(0); issue(1); issue(2);

    for (int c = 0; c < 32; c++) {
        if (c <= 29) cpwait2(); else if (c == 30) cpwait1(); else cpwait0();
        __syncthreads();
        bf* p = buf + (c % 3) * 4 * TS;
        mma_chunk<8>(acc, p, p + TS, p + 2 * TS, p + 3 * TS, wm, wn, lane);
        __syncthreads();
        if (c + 3 < 32) issue(c + 3);
    }

    #pragma unroll
    for (int i = 0; i < 2; i++)
        #pragma unroll
        for (int j = 0; j < 8; j++) {
            const int col = n0 + wn * 64 + j * 8 + ti * 2;
            const float b0v = bo[col], b1v = bo[col + 1];
            #pragma unroll
            for (int hr = 0; hr < 2; hr++) {
                const int row = m0 + wm * 32 + i * 16 + g + hr * 8;
                *(float2*)&out[(size_t)row * 1024 + col] =
                    make_float2(acc[i][j][hr * 2] + b0v, acc[i][j][hr * 2 + 1] + b1v);
            }
        }
}

// ============================================================
extern "C" void kernel_launch(void* const* d_in, const int* in_sizes, int n_in,
                              void* d_out, int out_size)
{
    const float* hs  = (const float*)d_in[0];
    const float* Wq  = (const float*)d_in[1];
    const float* bq  = (const float*)d_in[2];
    const float* Wk  = (const float*)d_in[3];
    const float* bk  = (const float*)d_in[4];
    const float* Wv  = (const float*)d_in[5];
    const float* bv  = (const float*)d_in[6];
    const float* Wo  = (const float*)d_in[7];
    const float* bo  = (const float*)d_in[8];
    const float* Wfq = (const float*)d_in[9];
    const float* bfq = (const float*)d_in[10];
    const float* Wfk = (const float*)d_in[11];
    const float* bfk = (const float*)d_in[12];
    float* out = (float*)d_out;

    const int SM_GEMM2 = 8 * TS * 2;                          // 81920 (2 CTA/SM)
    const int SM_GEMM3 = 12 * TS * 2;                         // 122880
    const int SM_TRUE  = 4 * TS * 2 + 12 * HT * 2;            // 102400 (2 CTA/SM)
    const int SM_PRED  = (4 + 6) * TS * 2;                    // 102400 (2 CTA/SM)
    const int SM_CTX   = 32768 + 4 * TS * 2 + 4 * HT * 2;     // 94208  (2 CTA/SM)
    const int SM_FEAT  = 4 * TS * 2 + 4 * HT * 2;             // 61440  (2 CTA/SM)
    cudaFuncSetAttribute(qkv_mma,     cudaFuncAttributeMaxDynamicSharedMemorySize, SM_GEMM2);
    cudaFuncSetAttribute(feat_mma,    cudaFuncAttributeMaxDynamicSharedMemorySize, SM_FEAT);
    cudaFuncSetAttribute(true_mma,    cudaFuncAttributeMaxDynamicSharedMemorySize, SM_TRUE);
    cudaFuncSetAttribute(pred_mma,    cudaFuncAttributeMaxDynamicSharedMemorySize, SM_PRED);
    cudaFuncSetAttribute(ctx_mma,     cudaFuncAttributeMaxDynamicSharedMemorySize, SM_CTX);
    cudaFuncSetAttribute(outproj_mma, cudaFuncAttributeMaxDynamicSharedMemorySize, SM_GEMM3);

    cudaStream_t s2;
    cudaStreamCreateWithFlags(&s2, cudaStreamNonBlocking);
    cudaEvent_t evQKV, evVT, evFKS, evJoin;
    cudaEventCreateWithFlags(&evQKV, cudaEventDisableTiming);
    cudaEventCreateWithFlags(&evVT,  cudaEventDisableTiming);
    cudaEventCreateWithFlags(&evFKS, cudaEventDisableTiming);
    cudaEventCreateWithFlags(&evJoin, cudaEventDisableTiming);

    ksplit_all<<<dim3(2048, 7), 256>>>(hs, Wq, Wk, Wv, Wo, Wfq, Wfk);
    qkv_mma<<<dim3(8, 16, 3), 256, SM_GEMM2>>>(bq, bk, bv);
    cudaEventRecord(evQKV, 0);

    // side stream: vtrans (needs only V from qkv), later pred after fksum
    cudaStreamWaitEvent(s2, evQKV, 0);
    vtrans<<<dim3(32, 8), 256, 0, s2>>>();
    cudaEventRecord(evVT, s2);

    // main: feat (MMA) -> fksum
    feat_mma<<<dim3(256, 2), 256, SM_FEAT>>>(bfq, bfk);
    fksum_kernel<<<32, 256>>>();
    cudaEventRecord(evFKS, 0);

    // side stream: pred (needs fkhi + fksum)
    cudaStreamWaitEvent(s2, evFKS, 0);
    pred_mma<<<dim3(8, 32), 256, SM_PRED, s2>>>(out + OFF_PRED);
    cudaEventRecord(evJoin, s2);

    // main chain: true, ctx (needs vt -> wait evVT), outproj
    true_mma<<<dim3(8, 32), 256, SM_TRUE>>>(out + OFF_TRUE);
    cudaStreamWaitEvent(0, evVT, 0);
    ctx_mma<<<dim3(8, 32), 256, SM_CTX>>>(out + OFF_TRUE);
    outproj_mma<<<dim3(8, 16), 256, SM_GEMM3>>>(bo, out);

    cudaStreamWaitEvent(0, evJoin, 0);
}

// round 17
// speedup vs baseline: 1.2057x; 1.0279x over previous
#include <cuda_runtime.h>
#include <cuda_bf16.h>
#include <cuda_fp16.h>
#include <math.h>
#include <stdint.h>

#define Ss 1024
#define Hh 16
#define BH 32
#define LD 40
typedef __nv_bfloat16 bf;
typedef __half hf;
typedef unsigned int u32;

#define OFF_PRED (2048*1024)
#define OFF_TRUE (OFF_PRED + 32*1024*1024)
#define TS (128*LD)
#define HT (64*LD)

// ---------------- scratch ----------------
__device__ hf g_qhi[BH*Ss*64], g_qlo[BH*Ss*64];     // fp16 splits, prescaled by 1/8
__device__ hf g_khi[BH*Ss*64], g_klo[BH*Ss*64];     // fp16 splits (lo used by feat only)
__device__ bf g_vhi[BH*Ss*64], g_vlo[BH*Ss*64];     // [bh][s][d]
__device__ bf g_vthi[BH*64*Ss], g_vtlo[BH*64*Ss];   // [bh][d][s]
__device__ bf g_Xhi[2048*1024], g_Xlo[2048*1024];
__device__ bf g_Whi[4][1024*1024], g_Wlo[4][1024*1024];
__device__ hf g_Wfhi[2][64*64], g_Wflo[2][64*64];   // hedgehog weights, fp16 splits
__device__ bf g_fqhi[BH*Ss*128];                    // bf16 features (hi only)
__device__ bf g_fkhi[BH*Ss*128];
__device__ bf g_chi[BH*Ss*64], g_clo[BH*Ss*64];
__device__ float g_fks[BH*128], g_inv[BH*Ss];

// ---------------- helpers ----------------
__device__ __forceinline__ u32 s2u(const void* p) {
    u32 r; asm("{ .reg .u64 t; cvta.to.shared.u64 t, %1; cvt.u32.u64 %0, t; }" : "=r"(r) : "l"(p)); return r;
}
__device__ __forceinline__ void cpa16(u32 dst, const void* src) {
    asm volatile("cp.async.cg.shared.global [%0], [%1], 16;" :: "r"(dst), "l"(src));
}
__device__ __forceinline__ void cpcommit() { asm volatile("cp.async.commit_group;" ::: "memory"); }
__device__ __forceinline__ void cpwait0() { asm volatile("cp.async.wait_group 0;" ::: "memory"); }
__device__ __forceinline__ void cpwait1() { asm volatile("cp.async.wait_group 1;" ::: "memory"); }
__device__ __forceinline__ void cpwait2() { asm volatile("cp.async.wait_group 2;" ::: "memory"); }
__device__ __forceinline__ void ldsm4(u32 a, u32& r0, u32& r1, u32& r2, u32& r3) {
    asm volatile("ldmatrix.sync.aligned.m8n8.x4.shared.b16 {%0,%1,%2,%3}, [%4];"
        : "=r"(r0), "=r"(r1), "=r"(r2), "=r"(r3) : "r"(a));
}
__device__ __forceinline__ void mmabf(float* d, const u32* a, const u32* b) {
    asm volatile("mma.sync.aligned.m16n8k16.row.col.f32.bf16.bf16.f32 "
        "{%0,%1,%2,%3}, {%4,%5,%6,%7}, {%8,%9}, {%0,%1,%2,%3};"
        : "+f"(d[0]), "+f"(d[1]), "+f"(d[2]), "+f"(d[3])
        : "r"(a[0]), "r"(a[1]), "r"(a[2]), "r"(a[3]), "r"(b[0]), "r"(b[1]));
}
__device__ __forceinline__ void mmahf(float* d, const u32* a, const u32* b) {
    asm volatile("mma.sync.aligned.m16n8k16.row.col.f32.f16.f16.f32 "
        "{%0,%1,%2,%3}, {%4,%5,%6,%7}, {%8,%9}, {%0,%1,%2,%3};"
        : "+f"(d[0]), "+f"(d[1]), "+f"(d[2]), "+f"(d[3])
        : "r"(a[0]), "r"(a[1]), "r"(a[2]), "r"(a[3]), "r"(b[0]), "r"(b[1]));
}
__device__ __forceinline__ void split2(float x, float y, u32& hi, u32& lo) {
    bf hx = __float2bfloat16(x), hy = __float2bfloat16(y);
    bf lx = __float2bfloat16(x - __bfloat162float(hx));
    bf ly = __float2bfloat16(y - __bfloat162float(hy));
    hi = (u32)__bfloat16_as_ushort(hx) | ((u32)__bfloat16_as_ushort(hy) << 16);
    lo = (u32)__bfloat16_as_ushort(lx) | ((u32)__bfloat16_as_ushort(ly) << 16);
}
__device__ __forceinline__ void split2f(float x, float y, u32& hi, u32& lo) {
    hf hx = __float2half_rn(x), hy = __float2half_rn(y);
    hf lx = __float2half_rn(x - __half2float(hx));
    hf ly = __float2half_rn(y - __half2float(hy));
    hi = (u32)__half_as_ushort(hx) | ((u32)__half_as_ushort(hy) << 16);
    lo = (u32)__half_as_ushort(lx) | ((u32)__half_as_ushort(ly) << 16);
}
__device__ __forceinline__ u32 packbf(float x, float y) {
    return (u32)__bfloat16_as_ushort(__float2bfloat16(x)) |
           ((u32)__bfloat16_as_ushort(__float2bfloat16(y)) << 16);
}
// fast exp on FMA pipe (rel err ~2e-6)
__device__ __forceinline__ float fexp(float x) {
    float t = x * 1.4426950408889634f;
    float f = t + 12582912.0f;
    int ib = __float_as_int(f);
    float n = f - 12582912.0f;
    float r = t - n;
    float p = 1.3333558e-3f;
    p = fmaf(p, r, 9.6181291e-3f);
    p = fmaf(p, r, 5.5504109e-2f);
    p = fmaf(p, r, 2.4022651e-1f);
    p = fmaf(p, r, 6.9314718e-1f);
    p = fmaf(p, r, 1.0f);
    return p * __int_as_float((ib << 23) + 0x3F800000);
}

// generic 2-byte tile loader (bf or hf)
__device__ __forceinline__ void ldtile32a(const void* __restrict__ gv, int ldg, u32 s, int rows) {
    const bf* g = (const bf*)gv;
    for (int i = threadIdx.x; i < rows * 4; i += 256) {
        int r = i >> 2, c = (i & 3) << 3;
        cpa16(s + (u32)((r * LD + c) << 1), g + (size_t)r * ldg + c);
    }
}

// 3-product hi/lo bf16 chunk
template<int NF>
__device__ __forceinline__ void mma_chunk(
    float (&acc)[2][NF][4],
    const bf* Ah, const bf* Al, const bf* Bh, const bf* Bl,
    int wm, int wn, int lane)
{
    const u32 ahb = s2u(Ah) + (u32)(wm * 32 * LD * 2);
    const u32 alb = s2u(Al) + (u32)(wm * 32 * LD * 2);
    const u32 bhb = s2u(Bh) + (u32)(wn * NF * 8 * LD * 2);
    const u32 blb = s2u(Bl) + (u32)(wn * NF * 8 * LD * 2);
    const u32 aoff = (u32)(((lane & 15) * LD + ((lane >> 4) << 3)) * 2);
    const u32 boff = (u32)((((lane & 7) + ((lane >> 4) << 3)) * LD + (((lane >> 3) & 1) << 3)) * 2);
    #pragma unroll
    for (int kk = 0; kk < 32; kk += 16) {
        u32 ah[2][4], al[2][4], bhf[NF][2], blf[NF][2];
        #pragma unroll
        for (int i = 0; i < 2; i++) {
            ldsm4(ahb + aoff + kk * 2 + i * 16 * LD * 2, ah[i][0], ah[i][1], ah[i][2], ah[i][3]);
            ldsm4(alb + aoff + kk * 2 + i * 16 * LD * 2, al[i][0], al[i][1], al[i][2], al[i][3]);
        }
        #pragma unroll
        for (int j = 0; j < NF; j += 2) {
            ldsm4(bhb + boff + kk * 2 + j * 8 * LD * 2, bhf[j][0], bhf[j][1], bhf[j+1][0], bhf[j+1][1]);
            ldsm4(blb + boff + kk * 2 + j * 8 * LD * 2, blf[j][0], blf[j][1], blf[j+1][0], blf[j+1][1]);
        }
        #pragma unroll
        for (int i = 0; i < 2; i++)
            #pragma unroll
            for (int j = 0; j < NF; j++) {
                mmabf(acc[i][j], ah[i], bhf[j]);
                mmabf(acc[i][j], ah[i], blf[j]);
                mmabf(acc[i][j], al[i], bhf[j]);
            }
    }
}

// 3-product hi/lo fp16 chunk (feat)
template<int NF>
__device__ __forceinline__ void mma_chunkh(
    float (&acc)[2][NF][4],
    const hf* Ah, const hf* Al, const hf* Bh, const hf* Bl,
    int wm, int wn, int lane)
{
    const u32 ahb = s2u(Ah) + (u32)(wm * 32 * LD * 2);
    const u32 alb = s2u(Al) + (u32)(wm * 32 * LD * 2);
    const u32 bhb = s2u(Bh) + (u32)(wn * NF * 8 * LD * 2);
    const u32 blb = s2u(Bl) + (u32)(wn * NF * 8 * LD * 2);
    const u32 aoff = (u32)(((lane & 15) * LD + ((lane >> 4) << 3)) * 2);
    const u32 boff = (u32)((((lane & 7) + ((lane >> 4) << 3)) * LD + (((lane >> 3) & 1) << 3)) * 2);
    #pragma unroll
    for (int kk = 0; kk < 32; kk += 16) {
        u32 ah[2][4], al[2][4], bhf[NF][2], blf[NF][2];
        #pragma unroll
        for (int i = 0; i < 2; i++) {
            ldsm4(ahb + aoff + kk * 2 + i * 16 * LD * 2, ah[i][0], ah[i][1], ah[i][2], ah[i][3]);
            ldsm4(alb + aoff + kk * 2 + i * 16 * LD * 2, al[i][0], al[i][1], al[i][2], al[i][3]);
        }
        #pragma unroll
        for (int j = 0; j < NF; j += 2) {
            ldsm4(bhb + boff + kk * 2 + j * 8 * LD * 2, bhf[j][0], bhf[j][1], bhf[j+1][0], bhf[j+1][1]);
            ldsm4(blb + boff + kk * 2 + j * 8 * LD * 2, blf[j][0], blf[j][1], blf[j+1][0], blf[j+1][1]);
        }
        #pragma unroll
        for (int i = 0; i < 2; i++)
            #pragma unroll
            for (int j = 0; j < NF; j++) {
                mmahf(acc[i][j], ah[i], bhf[j]);
                mmahf(acc[i][j], ah[i], blf[j]);
                mmahf(acc[i][j], al[i], bhf[j]);
            }
    }
}

// 2-product fp16 chunk (true): (Ah+Al) x B, B hi-only
template<int NF>
__device__ __forceinline__ void mma_chunkh2(
    float (&acc)[2][NF][4],
    const hf* Ah, const hf* Al, const hf* B,
    int wm, int wn, int lane)
{
    const u32 ahb = s2u(Ah) + (u32)(wm * 32 * LD * 2);
    const u32 alb = s2u(Al) + (u32)(wm * 32 * LD * 2);
    const u32 bb = s2u(B) + (u32)(wn * NF * 8 * LD * 2);
    const u32 aoff = (u32)(((lane & 15) * LD + ((lane >> 4) << 3)) * 2);
    const u32 boff = (u32)((((lane & 7) + ((lane >> 4) << 3)) * LD + (((lane >> 3) & 1) << 3)) * 2);
    #pragma unroll
    for (int kk = 0; kk < 32; kk += 16) {
        u32 ah[2][4], al[2][4], bfr[NF][2];
        #pragma unroll
        for (int i = 0; i < 2; i++) {
            ldsm4(ahb + aoff + kk * 2 + i * 16 * LD * 2, ah[i][0], ah[i][1], ah[i][2], ah[i][3]);
            ldsm4(alb + aoff + kk * 2 + i * 16 * LD * 2, al[i][0], al[i][1], al[i][2], al[i][3]);
        }
        #pragma unroll
        for (int j = 0; j < NF; j += 2)
            ldsm4(bb + boff + kk * 2 + j * 8 * LD * 2, bfr[j][0], bfr[j][1], bfr[j+1][0], bfr[j+1][1]);
        #pragma unroll
        for (int i = 0; i < 2; i++)
            #pragma unroll
            for (int j = 0; j < NF; j++) {
                mmahf(acc[i][j], ah[i], bfr[j]);
                mmahf(acc[i][j], al[i], bfr[j]);
            }
    }
}

// 1-product plain bf16 chunk (pred path)
template<int NF>
__device__ __forceinline__ void mma_chunk1(
    float (&acc)[2][NF][4],
    const bf* A, const bf* B,
    int wm, int wn, int lane)
{
    const u32 ab = s2u(A) + (u32)(wm * 32 * LD * 2);
    const u32 bb = s2u(B) + (u32)(wn * NF * 8 * LD * 2);
    const u32 aoff = (u32)(((lane & 15) * LD + ((lane >> 4) << 3)) * 2);
    const u32 boff = (u32)((((lane & 7) + ((lane >> 4) << 3)) * LD + (((lane >> 3) & 1) << 3)) * 2);
    #pragma unroll
    for (int kk = 0; kk < 32; kk += 16) {
        u32 a[2][4], bfr[NF][2];
        #pragma unroll
        for (int i = 0; i < 2; i++)
            ldsm4(ab + aoff + kk * 2 + i * 16 * LD * 2, a[i][0], a[i][1], a[i][2], a[i][3]);
        #pragma unroll
        for (int j = 0; j < NF; j += 2)
            ldsm4(bb + boff + kk * 2 + j * 8 * LD * 2, bfr[j][0], bfr[j][1], bfr[j+1][0], bfr[j+1][1]);
        #pragma unroll
        for (int i = 0; i < 2; i++)
            #pragma unroll
            for (int j = 0; j < NF; j++)
                mmabf(acc[i][j], a[i], bfr[j]);
    }
}

extern __shared__ __align__(16) char dynsm[];

// ============================================================
__global__ __launch_bounds__(256) void ksplit_all(
    const float* __restrict__ hs, const float* __restrict__ Wq,
    const float* __restrict__ Wk, const float* __restrict__ Wv,
    const float* __restrict__ Wo, const float* __restrict__ Wfq,
    const float* __restrict__ Wfk)
{
    const int y = blockIdx.y;
    const float* src; void* hi; void* lo; int n4;
    if (y == 0)      { src = hs;  hi = g_Xhi;     lo = g_Xlo;     n4 = 524288; }
    else if (y == 1) { src = Wq;  hi = g_Whi[0];  lo = g_Wlo[0];  n4 = 262144; }
    else if (y == 2) { src = Wk;  hi = g_Whi[1];  lo = g_Wlo[1];  n4 = 262144; }
    else if (y == 3) { src = Wv;  hi = g_Whi[2];  lo = g_Wlo[2];  n4 = 262144; }
    else if (y == 4) { src = Wo;  hi = g_Whi[3];  lo = g_Wlo[3];  n4 = 262144; }
    else if (y == 5) { src = Wfq; hi = g_Wfhi[0]; lo = g_Wflo[0]; n4 = 1024; }
    else             { src = Wfk; hi = g_Wfhi[1]; lo = g_Wflo[1]; n4 = 1024; }
    int i = blockIdx.x * 256 + threadIdx.x;
    if (i < n4) {
        float4 v = ((const float4*)src)[i];
        u32 h0, l0, h1, l1;
        if (y >= 5) {
            split2f(v.x, v.y, h0, l0);
            split2f(v.z, v.w, h1, l1);
        } else {
            split2(v.x, v.y, h0, l0);
            split2(v.z, v.w, h1, l1);
        }
        ((uint2*)hi)[i] = make_uint2(h0, h1);
        ((uint2*)lo)[i] = make_uint2(l0, l1);
    }
}

// ============================================================
// QKV. grid(8n,16m,3z). 2-stage pipeline, 80KB smem, 2 CTAs/SM.
// q/k epilogues emit fp16 splits; v stays bf16 splits.
// ============================================================
__global__ __launch_bounds__(256, 2) void qkv_mma(
    const float* __restrict__ bq, const float* __restrict__ bk, const float* __restrict__ bv)
{
    bf* buf = (bf*)dynsm;
    const int tid = threadIdx.x, lane = tid & 31, wid = tid >> 5;
    const int wm = wid & 3, wn = wid >> 2;
    const int g = lane >> 2, ti = lane & 3;
    const int z = blockIdx.z, m0 = blockIdx.y * 128, n0 = blockIdx.x * 128;
    const bf* Whi = g_Whi[z]; const bf* Wlo = g_Wlo[z];
    const float* bias = z == 0 ? bq : (z == 1 ? bk : bv);

    float acc[2][8][4];
    #pragma unroll
    for (int i = 0; i < 2; i++)
        #pragma unroll
        for (int j = 0; j < 8; j++)
            #pragma unroll
            for (int r = 0; r < 4; r++) acc[i][j][r] = 0.f;

    auto issue = [&](int c) {
        bf* p = buf + (c & 1) * 4 * TS;
        const int k0 = c * 32;
        ldtile32a(g_Xhi + (size_t)m0 * 1024 + k0, 1024, s2u(p), 128);
        ldtile32a(g_Xlo + (size_t)m0 * 1024 + k0, 1024, s2u(p + TS), 128);
        ldtile32a(Whi + (size_t)n0 * 1024 + k0, 1024, s2u(p + 2 * TS), 128);
        ldtile32a(Wlo + (size_t)n0 * 1024 + k0, 1024, s2u(p + 3 * TS), 128);
        cpcommit();
    };
    issue(0); issue(1);

    for (int c = 0; c < 32; c++) {
        if (c == 31) cpwait0(); else cpwait1();
        __syncthreads();
        bf* p = buf + (c & 1) * 4 * TS;
        mma_chunk<8>(acc, p, p + TS, p + 2 * TS, p + 3 * TS, wm, wn, lane);
        __syncthreads();
        if (c + 2 < 32) issue(c + 2);
    }

    #pragma unroll
    for (int i = 0; i < 2; i++)
        #pragma unroll
        for (int j = 0; j < 8; j++) {
            const int col = n0 + wn * 64 + j * 8 + ti * 2;
            const int h = col >> 6, d = col & 63;
            const float b0v = bias[col], b1v = bias[col + 1];
            #pragma unroll
            for (int hr = 0; hr < 2; hr++) {
                const int row = m0 + wm * 32 + i * 16 + g + hr * 8;
                const int b_ = row >> 10, s = row & 1023;
                const size_t ob = ((size_t)(b_ * Hh + h) * Ss + s) * 64 + d;
                const float v0 = acc[i][j][hr * 2] + b0v, v1 = acc[i][j][hr * 2 + 1] + b1v;
                u32 h2, l2;
                if (z == 0) {
                    split2f(v0 * 0.125f, v1 * 0.125f, h2, l2);
                    *(u32*)&g_qhi[ob] = h2; *(u32*)&g_qlo[ob] = l2;
                } else if (z == 1) {
                    split2f(v0, v1, h2, l2);
                    *(u32*)&g_khi[ob] = h2; *(u32*)&g_klo[ob] = l2;
                } else {
                    split2(v0, v1, h2, l2);
                    *(u32*)&g_vhi[ob] = h2; *(u32*)&g_vlo[ob] = l2;
                }
            }
        }
}

// ============================================================
// feature map as MMA (fp16 3-product): y = x @ Wf^T + b ; f = [fexp(y), fexp(-y)].
// ============================================================
__global__ __launch_bounds__(256, 2) void feat_mma(
    const float* __restrict__ bfq, const float* __restrict__ bfk)
{
    hf* ab = (hf*)dynsm;
    hf* bb = (hf*)dynsm + 4 * TS;
    const int tid = threadIdx.x, lane = tid & 31, wid = tid >> 5;
    const int wm = wid & 3, wn = wid >> 2;
    const int g = lane >> 2, ti = lane & 3;
    const int qk = blockIdx.y;
    const size_t m0 = (size_t)blockIdx.x * 128;
    const hf* sh = qk ? g_khi : g_qhi;
    const hf* sl = qk ? g_klo : g_qlo;
    const hf* wh = g_Wfhi[qk];
    const hf* wl = g_Wflo[qk];
    const float* bias = qk ? bfk : bfq;
    const float scale = qk ? 1.f : 8.f;
    bf* dh = qk ? g_fkhi : g_fqhi;

    ldtile32a(sh + m0 * 64,      64, s2u(ab),          128);
    ldtile32a(sl + m0 * 64,      64, s2u(ab + TS),     128);
    ldtile32a(sh + m0 * 64 + 32, 64, s2u(ab + 2 * TS), 128);
    ldtile32a(sl + m0 * 64 + 32, 64, s2u(ab + 3 * TS), 128);
    ldtile32a(wh,      64, s2u(bb),          64);
    ldtile32a(wl,      64, s2u(bb + HT),     64);
    ldtile32a(wh + 32, 64, s2u(bb + 2 * HT), 64);
    ldtile32a(wl + 32, 64, s2u(bb + 3 * HT), 64);
    cpcommit();
    cpwait0();
    __syncthreads();

    float acc[2][4][4];
    #pragma unroll
    for (int i = 0; i < 2; i++)
        #pragma unroll
        for (int j = 0; j < 4; j++)
            #pragma unroll
            for (int r = 0; r < 4; r++) acc[i][j][r] = 0.f;

    mma_chunkh<4>(acc, ab,          ab + TS,     bb,          bb + HT,     wm, wn, lane);
    mma_chunkh<4>(acc, ab + 2 * TS, ab + 3 * TS, bb + 2 * HT, bb + 3 * HT, wm, wn, lane);

    #pragma unroll
    for (int i = 0; i < 2; i++)
        #pragma unroll
        for (int j = 0; j < 4; j++) {
            const int col = wn * 32 + j * 8 + ti * 2;
            const float b0v = bias[col], b1v = bias[col + 1];
            #pragma unroll
            for (int hr = 0; hr < 2; hr++) {
                const size_t row = m0 + wm * 32 + i * 16 + g + hr * 8;
                const float y0 = acc[i][j][hr * 2] * scale + b0v;
                const float y1 = acc[i][j][hr * 2 + 1] * scale + b1v;
                *(u32*)&dh[row * 128 + col]      = packbf(fexp(y0), fexp(y1));
                *(u32*)&dh[row * 128 + 64 + col] = packbf(fexp(-y0), fexp(-y1));
            }
        }
}

// ============================================================
// V transpose (plane-wise, bf16): [bh][s][64] -> [bh][64][s]
// ============================================================
__global__ __launch_bounds__(256) void vtrans()
{
    __shared__ bf t[128][72];
    const int bh = blockIdx.x, s0 = blockIdx.y * 128, tid = threadIdx.x;
    #pragma unroll
    for (int a = 0; a < 2; a++) {
        const bf* src = a ? g_vlo : g_vhi;
        bf* dst = a ? g_vtlo : g_vthi;
        __syncthreads();
        for (int i = tid; i < 1024; i += 256) {
            int r = i >> 3, d8 = (i & 7) * 8;
            *(uint4*)&t[r][d8] = *(const uint4*)(src + ((size_t)bh * Ss + s0 + r) * 64 + d8);
        }
        __syncthreads();
        {
            const int d = tid & 63, sg = tid >> 6;
            __align__(16) bf tmp[32];
            #pragma unroll
            for (int s = 0; s < 32; s++) tmp[s] = t[sg * 32 + s][d];
            uint4* dp = (uint4*)(dst + ((size_t)bh * 64 + d) * Ss + s0 + sg * 32);
            #pragma unroll
            for (int q = 0; q < 4; q++) dp[q] = ((uint4*)tmp)[q];
        }
    }
}

// ============================================================
__global__ __launch_bounds__(256) void fksum_kernel()
{
    const int bh = blockIdx.x, tid = threadIdx.x;
    const int e = tid & 127, part = tid >> 7;
    const bf* fh = g_fkhi + (size_t)bh * Ss * 128;
    float s = 0.f;
    for (int r = part; r < 1024; r += 2)
        s += __bfloat162float(fh[(size_t)r * 128 + e]);
    __shared__ float sm[256];
    sm[tid] = s;
    __syncthreads();
    if (tid < 128) g_fks[bh * 128 + tid] = sm[tid] + sm[tid + 128];
}

// ============================================================
// true attention (fp16 2-product). Q resident (40KB), K hi-only
// 3-stage 64-n tiles (30KB) -> 72KB, 2 CTAs/SM. All-fexp.
// ============================================================
__global__ __launch_bounds__(256, 2) void true_mma(float* __restrict__ outT)
{
    hf* qb = (hf*)dynsm;
    hf* kb = (hf*)dynsm + 4 * TS;
    __shared__ float rs[128];
    const int tid = threadIdx.x, lane = tid & 31, wid = tid >> 5;
    const int wm = wid & 3, wn = wid >> 2;
    const int g = lane >> 2, ti = lane & 3;
    const int bh = blockIdx.y, m0 = blockIdx.x * 128;
    float* trow = outT + (size_t)bh * Ss * Ss;
    const hf* qh = g_qhi + ((size_t)bh * Ss + m0) * 64;
    const hf* ql = g_qlo + ((size_t)bh * Ss + m0) * 64;

    if (tid < 128) rs[tid] = 0.f;

    ldtile32a(qh,      64, s2u(qb),          128);
    ldtile32a(ql,      64, s2u(qb + TS),     128);
    ldtile32a(qh + 32, 64, s2u(qb + 2 * TS), 128);
    ldtile32a(ql + 32, 64, s2u(qb + 3 * TS), 128);
    cpcommit();

    auto issueK = [&](int nt) {
        hf* p = kb + (nt % 3) * 2 * HT;
        const hf* kh = g_khi + ((size_t)bh * Ss + nt * 64) * 64;
        ldtile32a(kh,      64, s2u(p),      64);
        ldtile32a(kh + 32, 64, s2u(p + HT), 64);
        cpcommit();
    };
    issueK(0); issueK(1); issueK(2);

    float rsum[4] = {0.f, 0.f, 0.f, 0.f};
    for (int nt = 0; nt < 16; nt++) {
        if (nt <= 13) cpwait2(); else if (nt == 14) cpwait1(); else cpwait0();
        __syncthreads();
        float acc[2][4][4];
        #pragma unroll
        for (int i = 0; i < 2; i++)
            #pragma unroll
            for (int j = 0; j < 4; j++)
                #pragma unroll
                for (int r = 0; r < 4; r++) acc[i][j][r] = 0.f;

        hf* p = kb + (nt % 3) * 2 * HT;
        mma_chunkh2<4>(acc, qb,          qb + TS,     p,      wm, wn, lane);
        mma_chunkh2<4>(acc, qb + 2 * TS, qb + 3 * TS, p + HT, wm, wn, lane);
        __syncthreads();
        if (nt + 3 < 16) issueK(nt + 3);

        const int n0 = nt * 64;
        #pragma unroll
        for (int i = 0; i < 2; i++)
            #pragma unroll
            for (int j = 0; j < 4; j++) {
                float e0 = fexp(acc[i][j][0]), e1 = fexp(acc[i][j][1]);
                float e2 = fexp(acc[i][j][2]), e3 = fexp(acc[i][j][3]);
                rsum[i * 2]     += e0 + e1;
                rsum[i * 2 + 1] += e2 + e3;
                const int col = n0 + wn * 32 + j * 8 + ti * 2;
                const int row = m0 + wm * 32 + i * 16 + g;
                *(float2*)&trow[(size_t)row * 1024 + col]       = make_float2(e0, e1);
                *(float2*)&trow[(size_t)(row + 8) * 1024 + col] = make_float2(e2, e3);
            }
    }

    #pragma unroll
    for (int r = 0; r < 4; r++) {
        float v = rsum[r];
        v += __shfl_xor_sync(0xffffffffu, v, 1);
        v += __shfl_xor_sync(0xffffffffu, v, 2);
        if (ti == 0) atomicAdd(&rs[wm * 32 + (r >> 1) * 16 + (r & 1) * 8 + g], v);
    }
    __syncthreads();
    if (tid < 128) g_inv[bh * Ss + m0 + tid] = 1.f / rs[tid];
}

// ============================================================
// pred: hi-only bf16 features, denom computed in-kernel from smem fq.
// fq resident 40KB, fk 3-stage half-tiles. 100KB smem -> 2 CTAs/SM.
// ============================================================
__global__ __launch_bounds__(256, 2) void pred_mma(float* __restrict__ outP)
{
    bf* fq = (bf*)dynsm;
    bf* kb = (bf*)dynsm + 4 * TS;
    __shared__ float fks_sm[128];
    __shared__ float pinv_sm[128];
    const int tid = threadIdx.x, lane = tid & 31, wid = tid >> 5;
    const int wm = wid & 3, wn = wid >> 2;
    const int g = lane >> 2, ti = lane & 3;
    const int bh = blockIdx.y, m0 = blockIdx.x * 128;
    float* prow = outP + (size_t)bh * Ss * Ss;
    const bf* fqh = g_fqhi + ((size_t)bh * Ss + m0) * 128;

    if (tid < 128) fks_sm[tid] = g_fks[bh * 128 + tid];

    #pragma unroll
    for (int kc = 0; kc < 4; kc++)
        ldtile32a(fqh + kc * 32, 128, s2u(fq + kc * TS), 128);
    cpcommit();

    auto issueFK = [&](int st) {
        bf* p = kb + (st % 3) * 2 * TS;
        const int nt = st >> 1, half = st & 1;
        const bf* kh = g_fkhi + ((size_t)bh * Ss + nt * 128) * 128 + half * 64;
        ldtile32a(kh,      128, s2u(p),      128);
        ldtile32a(kh + 32, 128, s2u(p + TS), 128);
        cpcommit();
    };
    issueFK(0); issueFK(1); issueFK(2);

    float pv[4];
    float acc[2][8][4];
    for (int st = 0; st < 16; st++) {
        const int nt = st >> 1, half = st & 1;
        if (half == 0) {
            #pragma unroll
            for (int i = 0; i < 2; i++)
                #pragma unroll
                for (int j = 0; j < 8; j++)
                    #pragma unroll
                    for (int r = 0; r < 4; r++) acc[i][j][r] = 0.f;
        }
        if (st <= 13) cpwait2(); else if (st == 14) cpwait1(); else cpwait0();
        __syncthreads();

        if (st == 0) {
            if (tid < 128) {
                float d = 0.f;
                #pragma unroll
                for (int kc = 0; kc < 4; kc++) {
                    const bf* fr = fq + kc * TS + tid * LD;
                    #pragma unroll
                    for (int kk = 0; kk < 32; kk++)
                        d += __bfloat162float(fr[kk]) * fks_sm[kc * 32 + kk];
                }
                pinv_sm[tid] = 1.f / d;
            }
            __syncthreads();
            #pragma unroll
            for (int r = 0; r < 4; r++)
                pv[r] = pinv_sm[wm * 32 + (r >> 1) * 16 + (r & 1) * 8 + g];
        }

        bf* p = kb + (st % 3) * 2 * TS;
        const int kc = half * 2;
        mma_chunk1<8>(acc, fq + kc * TS,       p,      wm, wn, lane);
        mma_chunk1<8>(acc, fq + (kc + 1) * TS, p + TS, wm, wn, lane);
        __syncthreads();
        if (st + 3 < 16) issueFK(st + 3);

        if (half == 1) {
            const int n0 = nt * 128;
            #pragma unroll
            for (int i = 0; i < 2; i++)
                #pragma unroll
                for (int j = 0; j < 8; j++) {
                    const int col = n0 + wn * 64 + j * 8 + ti * 2;
                    const int row = m0 + wm * 32 + i * 16 + g;
                    *(float2*)&prow[(size_t)row * 1024 + col] =
                        make_float2(acc[i][j][0] * pv[i * 2], acc[i][j][1] * pv[i * 2]);
                    *(float2*)&prow[(size_t)(row + 8) * 1024 + col] =
                        make_float2(acc[i][j][2] * pv[i * 2 + 1], acc[i][j][3] * pv[i * 2 + 1]);
                }
        }
    }
}

// ============================================================
// ctx = Pnorm @ V (normalize trow in place). 94KB smem, 2 CTAs/SM.
// ============================================================
__global__ __launch_bounds__(256, 2) void ctx_mma(float* __restrict__ outT)
{
    float* tr = (float*)dynsm;
    bf* ab = (bf*)(dynsm + 32768);
    bf* bb = (bf*)(dynsm + 32768 + 2 * TS * 2);
    __shared__ float invsm[128];
    const int tid = threadIdx.x, lane = tid & 31, wid = tid >> 5;
    const int wm = wid & 3, wn = wid >> 2;
    const int g = lane >> 2, ti = lane & 3;
    const int bh = blockIdx.y, m0 = blockIdx.x * 128;
    float* trow = outT + (size_t)bh * Ss * Ss;

    if (tid < 128) invsm[tid] = g_inv[bh * Ss + m0 + tid];

    auto issue = [&](int c) {
        const int st = c & 1;
        u32 ts = s2u(tr + st * 4096);
        for (int i = tid; i < 1024; i += 256) {
            int r = i >> 3, c4 = (i & 7) * 4;
            cpa16(ts + (u32)((r * 32 + c4) * 4), &trow[(size_t)(m0 + r) * 1024 + c * 32 + c4]);
        }
        bf* p = bb + st * 2 * HT;
        ldtile32a(g_vthi + (size_t)bh * 64 * Ss + c * 32, Ss, s2u(p), 64);
        ldtile32a(g_vtlo + (size_t)bh * 64 * Ss + c * 32, Ss, s2u(p + HT), 64);
        cpcommit();
    };
    issue(0); issue(1);

    float acc[2][4][4];
    #pragma unroll
    for (int i = 0; i < 2; i++)
        #pragma unroll
        for (int j = 0; j < 4; j++)
            #pragma unroll
            for (int r = 0; r < 4; r++) acc[i][j][r] = 0.f;

    for (int c = 0; c < 32; c++) {
        if (c == 31) cpwait0(); else cpwait1();
        __syncthreads();
        const int st = c & 1;
        float* trs = tr + st * 4096;
        for (int i = tid; i < 1024; i += 256) {
            int r = i >> 3, c4 = (i & 7) * 4;
            float4 v = *(float4*)&trs[r * 32 + c4];
            float iv = invsm[r];
            v.x *= iv; v.y *= iv; v.z *= iv; v.w *= iv;
            *(float4*)&trow[(size_t)(m0 + r) * 1024 + c * 32 + c4] = v;
            u32 h0, l0, h1, l1;
            split2(v.x, v.y, h0, l0);
            split2(v.z, v.w, h1, l1);
            *(u32*)&ab[r * LD + c4] = h0;      *(u32*)&ab[r * LD + c4 + 2] = h1;
            *(u32*)&ab[TS + r * LD + c4] = l0; *(u32*)&ab[TS + r * LD + c4 + 2] = l1;
        }
        __syncthreads();
        bf* p = bb + st * 2 * HT;
        mma_chunk<4>(acc, ab, ab + TS, p, p + HT, wm, wn, lane);
        __syncthreads();
        if (c + 2 < 32) issue(c + 2);
    }

    #pragma unroll
    for (int i = 0; i < 2; i++)
        #pragma unroll
        for (int j = 0; j < 4; j++) {
            const int col = wn * 32 + j * 8 + ti * 2;
            #pragma unroll
            for (int hr = 0; hr < 2; hr++) {
                const int row = m0 + wm * 32 + i * 16 + g + hr * 8;
                const size_t ob = ((size_t)bh * Ss + row) * 64 + col;
                u32 h2, l2;
                split2(acc[i][j][hr * 2], acc[i][j][hr * 2 + 1], h2, l2);
                *(u32*)&g_chi[ob] = h2; *(u32*)&g_clo[ob] = l2;
            }
        }
}

// ============================================================
// outproj. grid(8n,16m). 3-stage pipeline.
// ============================================================
__global__ __launch_bounds__(256) void outproj_mma(const float* __restrict__ bo, float* __restrict__ out)
{
    bf* buf = (bf*)dynsm;
    const int tid = threadIdx.x, lane = tid & 31, wid = tid >> 5;
    const int wm = wid & 3, wn = wid >> 2;
    const int g = lane >> 2, ti = lane & 3;
    const int m0 = blockIdx.y * 128, n0 = blockIdx.x * 128;
    const int b_ = m0 >> 10, s0 = m0 & 1023;

    float acc[2][8][4];
    #pragma unroll
    for (int i = 0; i < 2; i++)
        #pragma unroll
        for (int j = 0; j < 8; j++)
            #pragma unroll
            for (int r = 0; r < 4; r++) acc[i][j][r] = 0.f;

    auto issue = [&](int c) {
        bf* p = buf + (c % 3) * 4 * TS;
        const int k0 = c * 32;
        const int h = k0 >> 6, doff = k0 & 63;
        const size_t abase = ((size_t)(b_ * Hh + h) * Ss + s0) * 64 + doff;
        ldtile32a(g_chi + abase, 64, s2u(p), 128);
        ldtile32a(g_clo + abase, 64, s2u(p + TS), 128);
        ldtile32a(g_Whi[3] + (size_t)n0 * 1024 + k0, 1024, s2u(p + 2 * TS), 128);
        ldtile32a(g_Wlo[3] + (size_t)n0 * 1024 + k0, 1024, s2u(p + 3 * TS), 128);
        cpcommit();
    };
    issue(0); issue(1); issue(2);

    for (int c = 0; c < 32; c++) {
        if (c <= 29) cpwait2(); else if (c == 30) cpwait1(); else cpwait0();
        __syncthreads();
        bf* p = buf + (c % 3) * 4 * TS;
        mma_chunk<8>(acc, p, p + TS, p + 2 * TS, p + 3 * TS, wm, wn, lane);
        __syncthreads();
        if (c + 3 < 32) issue(c + 3);
    }

    #pragma unroll
    for (int i = 0; i < 2; i++)
        #pragma unroll
        for (int j = 0; j < 8; j++) {
            const int col = n0 + wn * 64 + j * 8 + ti * 2;
            const float b0v = bo[col], b1v = bo[col + 1];
            #pragma unroll
            for (int hr = 0; hr < 2; hr++) {
                const int row = m0 + wm * 32 + i * 16 + g + hr * 8;
                *(float2*)&out[(size_t)row * 1024 + col] =
                    make_float2(acc[i][j][hr * 2] + b0v, acc[i][j][hr * 2 + 1] + b1v);
            }
        }
}

// ============================================================
extern "C" void kernel_launch(void* const* d_in, const int* in_sizes, int n_in,
                              void* d_out, int out_size)
{
    const float* hs  = (const float*)d_in[0];
    const float* Wq  = (const float*)d_in[1];
    const float* bq  = (const float*)d_in[2];
    const float* Wk  = (const float*)d_in[3];
    const float* bk  = (const float*)d_in[4];
    const float* Wv  = (const float*)d_in[5];
    const float* bv  = (const float*)d_in[6];
    const float* Wo  = (const float*)d_in[7];
    const float* bo  = (const float*)d_in[8];
    const float* Wfq = (const float*)d_in[9];
    const float* bfq = (const float*)d_in[10];
    const float* Wfk = (const float*)d_in[11];
    const float* bfk = (const float*)d_in[12];
    float* out = (float*)d_out;

    const int SM_GEMM2 = 8 * TS * 2;                          // 81920 (2 CTA/SM)
    const int SM_GEMM3 = 12 * TS * 2;                         // 122880
    const int SM_TRUE  = 4 * TS * 2 + 6 * HT * 2;             // 71680 (2 CTA/SM)
    const int SM_PRED  = (4 + 6) * TS * 2;                    // 102400 (2 CTA/SM)
    const int SM_CTX   = 32768 + 4 * TS * 2 + 4 * HT * 2;     // 94208  (2 CTA/SM)
    const int SM_FEAT  = 4 * TS * 2 + 4 * HT * 2;             // 61440  (2 CTA/SM)
    cudaFuncSetAttribute(qkv_mma,     cudaFuncAttributeMaxDynamicSharedMemorySize, SM_GEMM2);
    cudaFuncSetAttribute(feat_mma,    cudaFuncAttributeMaxDynamicSharedMemorySize, SM_FEAT);
    cudaFuncSetAttribute(true_mma,    cudaFuncAttributeMaxDynamicSharedMemorySize, SM_TRUE);
    cudaFuncSetAttribute(pred_mma,    cudaFuncAttributeMaxDynamicSharedMemorySize, SM_PRED);
    cudaFuncSetAttribute(ctx_mma,     cudaFuncAttributeMaxDynamicSharedMemorySize, SM_CTX);
    cudaFuncSetAttribute(outproj_mma, cudaFuncAttributeMaxDynamicSharedMemorySize, SM_GEMM3);

    cudaStream_t s2;
    cudaStreamCreateWithFlags(&s2, cudaStreamNonBlocking);
    cudaEvent_t evQKV, evVT, evFKS, evJoin;
    cudaEventCreateWithFlags(&evQKV, cudaEventDisableTiming);
    cudaEventCreateWithFlags(&evVT,  cudaEventDisableTiming);
    cudaEventCreateWithFlags(&evFKS, cudaEventDisableTiming);
    cudaEventCreateWithFlags(&evJoin, cudaEventDisableTiming);

    ksplit_all<<<dim3(2048, 7), 256>>>(hs, Wq, Wk, Wv, Wo, Wfq, Wfk);
    qkv_mma<<<dim3(8, 16, 3), 256, SM_GEMM2>>>(bq, bk, bv);
    cudaEventRecord(evQKV, 0);

    // side stream: vtrans (needs only V from qkv), later pred after fksum
    cudaStreamWaitEvent(s2, evQKV, 0);
    vtrans<<<dim3(32, 8), 256, 0, s2>>>();
    cudaEventRecord(evVT, s2);

    // main: feat (fp16 MMA) -> fksum
    feat_mma<<<dim3(256, 2), 256, SM_FEAT>>>(bfq, bfk);
    fksum_kernel<<<32, 256>>>();
    cudaEventRecord(evFKS, 0);

    // side stream: pred (needs fkhi + fksum)
    cudaStreamWaitEvent(s2, evFKS, 0);
    pred_mma<<<dim3(8, 32), 256, SM_PRED, s2>>>(out + OFF_PRED);
    cudaEventRecord(evJoin, s2);

    // main chain: true (fp16 2-product), ctx (needs vt), outproj
    true_mma<<<dim3(8, 32), 256, SM_TRUE>>>(out + OFF_TRUE);
    cudaStreamWaitEvent(0, evVT, 0);
    ctx_mma<<<dim3(8, 32), 256, SM_CTX>>>(out + OFF_TRUE);
    outproj_mma<<<dim3(8, 16), 256, SM_GEMM3>>>(bo, out);

    cudaStreamWaitEvent(0, evJoin, 0);
}